// round 1
// baseline (speedup 1.0000x reference)
#include <cuda_runtime.h>

#define B_ 4
#define N_ 8192
#define E_ 1024
#define D_ 64
#define M_ (B_*N_)          // 32768 rows of X
#define SPLITS 64
#define ROWS_PER_SPLIT (N_/SPLITS)   // 128
#define SCALE_ 0.21650635094610965f  // sqrt(3/64)

// Scratch (device globals; no allocation allowed)
__device__ float g_Q[M_*D_];
__device__ float g_K[M_*D_];
__device__ float g_V[M_*D_];
__device__ float g_epart[B_*SPLITS*D_*D_];
__device__ float g_W2[B_*D_*E_];

// ---------------------------------------------------------------------------
// K1: QKV projection.  Out[m][d] = sum_e X[m][e] * W[d][e]
// BM=128, BN=64(=D), BK=16, 256 threads, 8x4 microtile per thread.
// ---------------------------------------------------------------------------
__global__ __launch_bounds__(256) void qkv_kernel(
    const float* __restrict__ X,
    const float* __restrict__ Wq,
    const float* __restrict__ Wk,
    const float* __restrict__ Wv)
{
    constexpr int BM = 128, BK = 16;
    __shared__ float As[BK][BM];   // [k][m]
    __shared__ float Bs[BK][D_];   // [k][n]

    const float* W   = (blockIdx.y == 0) ? Wq : (blockIdx.y == 1 ? Wk : Wv);
    float*       Out = (blockIdx.y == 0) ? g_Q : (blockIdx.y == 1 ? g_K : g_V);

    const int m0  = blockIdx.x * BM;
    const int tid = threadIdx.x;
    const int ty  = tid >> 4;   // 0..15 -> m group of 8
    const int tx  = tid & 15;   // 0..15 -> n group of 4

    float acc[8][4];
    #pragma unroll
    for (int i = 0; i < 8; i++)
        #pragma unroll
        for (int j = 0; j < 4; j++) acc[i][j] = 0.f;

    for (int k0 = 0; k0 < E_; k0 += BK) {
        // Load X tile 128x16 (transposed into As)
        #pragma unroll
        for (int i = 0; i < 2; i++) {
            int idx = tid * 2 + i;
            int r   = idx >> 2;
            int c4  = idx & 3;
            float4 v = *(const float4*)&X[(size_t)(m0 + r) * E_ + k0 + c4 * 4];
            As[c4*4+0][r] = v.x;
            As[c4*4+1][r] = v.y;
            As[c4*4+2][r] = v.z;
            As[c4*4+3][r] = v.w;
        }
        // Load W tile 64x16 (transposed into Bs)
        {
            int r  = tid >> 2;   // 0..63
            int c4 = tid & 3;
            float4 v = *(const float4*)&W[(size_t)r * E_ + k0 + c4 * 4];
            Bs[c4*4+0][r] = v.x;
            Bs[c4*4+1][r] = v.y;
            Bs[c4*4+2][r] = v.z;
            Bs[c4*4+3][r] = v.w;
        }
        __syncthreads();

        #pragma unroll
        for (int k = 0; k < BK; k++) {
            float a[8], b[4];
            *(float4*)&a[0] = *(const float4*)&As[k][ty * 8];
            *(float4*)&a[4] = *(const float4*)&As[k][ty * 8 + 4];
            *(float4*)&b[0] = *(const float4*)&Bs[k][tx * 4];
            #pragma unroll
            for (int i = 0; i < 8; i++)
                #pragma unroll
                for (int j = 0; j < 4; j++)
                    acc[i][j] += a[i] * b[j];
        }
        __syncthreads();
    }

    #pragma unroll
    for (int i = 0; i < 8; i++) {
        float4 v = make_float4(acc[i][0], acc[i][1], acc[i][2], acc[i][3]);
        *(float4*)&Out[(size_t)(m0 + ty * 8 + i) * D_ + tx * 4] = v;
    }
}

// ---------------------------------------------------------------------------
// K2: energy partials.  epart[b][s][d][e] = sum over this split's n of K*V
// grid (SPLITS, B), 256 threads, each thread 4x4 of the 64x64 output.
// ---------------------------------------------------------------------------
__global__ __launch_bounds__(256) void energy_kernel()
{
    const int s = blockIdx.x;
    const int b = blockIdx.y;
    const float* Kb = g_K + (size_t)b * N_ * D_;
    const float* Vb = g_V + (size_t)b * N_ * D_;
    const int n_base = s * ROWS_PER_SPLIT;

    __shared__ float Ks[16][D_];
    __shared__ float Vs[16][D_];

    const int tid = threadIdx.x;
    const int ty  = tid >> 4;
    const int tx  = tid & 15;

    float acc[4][4];
    #pragma unroll
    for (int i = 0; i < 4; i++)
        #pragma unroll
        for (int j = 0; j < 4; j++) acc[i][j] = 0.f;

    for (int c = 0; c < ROWS_PER_SPLIT; c += 16) {
        int r  = tid >> 4;   // 0..15
        int c4 = tid & 15;   // 0..15
        *(float4*)&Ks[r][c4 * 4] = *(const float4*)&Kb[(size_t)(n_base + c + r) * D_ + c4 * 4];
        *(float4*)&Vs[r][c4 * 4] = *(const float4*)&Vb[(size_t)(n_base + c + r) * D_ + c4 * 4];
        __syncthreads();
        #pragma unroll
        for (int n = 0; n < 16; n++) {
            float kv[4], vv[4];
            *(float4*)&kv[0] = *(const float4*)&Ks[n][ty * 4];
            *(float4*)&vv[0] = *(const float4*)&Vs[n][tx * 4];
            #pragma unroll
            for (int i = 0; i < 4; i++)
                #pragma unroll
                for (int j = 0; j < 4; j++)
                    acc[i][j] += kv[i] * vv[j];
        }
        __syncthreads();
    }

    float* ep = g_epart + ((size_t)(b * SPLITS + s)) * (D_ * D_);
    #pragma unroll
    for (int i = 0; i < 4; i++) {
        float4 v = make_float4(acc[i][0], acc[i][1], acc[i][2], acc[i][3]);
        *(float4*)&ep[(ty * 4 + i) * D_ + tx * 4] = v;
    }
}

// ---------------------------------------------------------------------------
// K3: reduce partials + fold wo:  W2[b][d][e] = scale * sum_d2 energy[b][d][d2]*wo[e][d2]
// grid (D, B), 256 threads.
// ---------------------------------------------------------------------------
__global__ __launch_bounds__(256) void w2_kernel(const float* __restrict__ Wo)
{
    const int d = blockIdx.x;
    const int b = blockIdx.y;
    __shared__ float part[4][D_];
    __shared__ float row[D_];

    const int tid = threadIdx.x;
    const int d2  = tid & 63;
    const int sg  = tid >> 6;   // 0..3

    float sum = 0.f;
    for (int s = sg; s < SPLITS; s += 4)
        sum += g_epart[((size_t)(b * SPLITS + s)) * (D_ * D_) + d * D_ + d2];
    part[sg][d2] = sum;
    __syncthreads();
    if (tid < D_)
        row[tid] = (part[0][tid] + part[1][tid] + part[2][tid] + part[3][tid]) * SCALE_;
    __syncthreads();

    float* w2row = g_W2 + ((size_t)(b * D_ + d)) * E_;
    for (int e = tid; e < E_; e += 256) {
        const float4* wo4 = (const float4*)&Wo[(size_t)e * D_];
        float acc = 0.f;
        #pragma unroll
        for (int k4 = 0; k4 < D_ / 4; k4++) {
            float4 w = wo4[k4];
            acc += row[k4*4+0] * w.x + row[k4*4+1] * w.y
                 + row[k4*4+2] * w.z + row[k4*4+3] * w.w;
        }
        w2row[e] = acc;
    }
}

// ---------------------------------------------------------------------------
// K4: out[b][m][e] = sum_d Q[b][m][d] * W2[b][d][e]
// BM=64, BN=64, BK=64 (whole K), 256 threads, 4x4 microtile.
// ---------------------------------------------------------------------------
__global__ __launch_bounds__(256) void out_kernel(float* __restrict__ Out)
{
    __shared__ float Qs[D_][D_];   // [m][k]
    __shared__ float Ws[D_][D_];   // [k][e]

    const int m0 = blockIdx.x * 64;
    const int e0 = blockIdx.y * 64;
    const int b  = blockIdx.z;
    const float* Qb  = g_Q  + (size_t)b * N_ * D_;
    const float* W2b = g_W2 + (size_t)b * D_ * E_;

    const int tid = threadIdx.x;
    #pragma unroll
    for (int i = 0; i < 4; i++) {
        int idx = i * 256 + tid;
        int r   = idx >> 4;
        int c4  = idx & 15;
        *(float4*)&Qs[r][c4 * 4] = *(const float4*)&Qb[(size_t)(m0 + r) * D_ + c4 * 4];
        *(float4*)&Ws[r][c4 * 4] = *(const float4*)&W2b[(size_t)r * E_ + e0 + c4 * 4];
    }
    __syncthreads();

    const int ty = tid >> 4;
    const int tx = tid & 15;
    float acc[4][4];
    #pragma unroll
    for (int i = 0; i < 4; i++)
        #pragma unroll
        for (int j = 0; j < 4; j++) acc[i][j] = 0.f;

    #pragma unroll 16
    for (int k = 0; k < D_; k++) {
        float a[4], bb[4];
        a[0] = Qs[ty*4+0][k];
        a[1] = Qs[ty*4+1][k];
        a[2] = Qs[ty*4+2][k];
        a[3] = Qs[ty*4+3][k];
        *(float4*)&bb[0] = *(const float4*)&Ws[k][tx * 4];
        #pragma unroll
        for (int i = 0; i < 4; i++)
            #pragma unroll
            for (int j = 0; j < 4; j++)
                acc[i][j] += a[i] * bb[j];
    }

    #pragma unroll
    for (int i = 0; i < 4; i++) {
        float4 v = make_float4(acc[i][0], acc[i][1], acc[i][2], acc[i][3]);
        *(float4*)&Out[((size_t)b * N_ + m0 + ty * 4 + i) * E_ + e0 + tx * 4] = v;
    }
}

// ---------------------------------------------------------------------------
extern "C" void kernel_launch(void* const* d_in, const int* in_sizes, int n_in,
                              void* d_out, int out_size)
{
    const float* x  = (const float*)d_in[0];
    const float* wq = (const float*)d_in[1];
    const float* wk = (const float*)d_in[2];
    const float* wv = (const float*)d_in[3];
    const float* wo = (const float*)d_in[4];
    float* out = (float*)d_out;

    qkv_kernel   <<<dim3(M_ / 128, 3), 256>>>(x, wq, wk, wv);
    energy_kernel<<<dim3(SPLITS, B_), 256>>>();
    w2_kernel    <<<dim3(D_, B_), 256>>>(wo);
    out_kernel   <<<dim3(N_ / 64, E_ / 64, B_), 256>>>(out);
}

// round 2
// speedup vs baseline: 1.0244x; 1.0244x over previous
#include <cuda_runtime.h>

#define B_ 4
#define N_ 8192
#define E_ 1024
#define D_ 64
#define M_ (B_*N_)          // 32768 rows of X
#define SPLITS 64
#define ROWS_PER_SPLIT (N_/SPLITS)   // 128
#define SCALE_ 0.21650635094610965f  // sqrt(3/64)

using u64 = unsigned long long;

// Packed f32x2 helpers (sm_100+). fma.rn.f32x2 = 2 IEEE fp32 FMAs in one inst.
__device__ __forceinline__ u64 pack2(float lo, float hi) {
    u64 r; asm("mov.b64 %0, {%1, %2};" : "=l"(r) : "f"(lo), "f"(hi)); return r;
}
__device__ __forceinline__ void unpack2(u64 v, float& lo, float& hi) {
    asm("mov.b64 {%0, %1}, %2;" : "=f"(lo), "=f"(hi) : "l"(v));
}
__device__ __forceinline__ u64 ffma2(u64 a, u64 b, u64 c) {
    u64 d; asm("fma.rn.f32x2 %0, %1, %2, %3;" : "=l"(d) : "l"(a), "l"(b), "l"(c)); return d;
}

// Scratch (device globals; no allocation allowed)
__device__ float g_Q[M_*D_];
__device__ float g_K[M_*D_];
__device__ float g_V[M_*D_];
__device__ float g_epart[B_*SPLITS*D_*D_];
__device__ float g_W2[B_*D_*E_];

// ---------------------------------------------------------------------------
// K1: QKV projection.  Out[m][d] = sum_e X[m][e] * W[d][e]
// BM=128, BN=64(=D), BK=16, 256 threads.
// Microtile 8m x 4n per thread, computed as 4 packed m-pairs x 4 n (FFMA2).
// ---------------------------------------------------------------------------
__global__ __launch_bounds__(256) void qkv_kernel(
    const float* __restrict__ X,
    const float* __restrict__ Wq,
    const float* __restrict__ Wk,
    const float* __restrict__ Wv)
{
    constexpr int BM = 128, BK = 16;
    __shared__ float As[BK][BM];   // [k][m]  (m contiguous -> packed pair loads)
    __shared__ float Bs[BK][D_];   // [k][n]

    const float* W   = (blockIdx.y == 0) ? Wq : (blockIdx.y == 1 ? Wk : Wv);
    float*       Out = (blockIdx.y == 0) ? g_Q : (blockIdx.y == 1 ? g_K : g_V);

    const int m0  = blockIdx.x * BM;
    const int tid = threadIdx.x;
    const int ty  = tid >> 4;   // 0..15 -> m group of 8
    const int tx  = tid & 15;   // 0..15 -> n group of 4

    u64 acc[4][4];               // [m-pair][n]
    #pragma unroll
    for (int i = 0; i < 4; i++)
        #pragma unroll
        for (int j = 0; j < 4; j++) acc[i][j] = 0ull;

    for (int k0 = 0; k0 < E_; k0 += BK) {
        // Load X tile 128x16 (transposed into As)
        #pragma unroll
        for (int i = 0; i < 2; i++) {
            int idx = tid * 2 + i;
            int r   = idx >> 2;
            int c4  = idx & 3;
            float4 v = *(const float4*)&X[(size_t)(m0 + r) * E_ + k0 + c4 * 4];
            As[c4*4+0][r] = v.x;
            As[c4*4+1][r] = v.y;
            As[c4*4+2][r] = v.z;
            As[c4*4+3][r] = v.w;
        }
        // Load W tile 64x16 (transposed into Bs)
        {
            int r  = tid >> 2;   // 0..63
            int c4 = tid & 3;
            float4 v = *(const float4*)&W[(size_t)r * E_ + k0 + c4 * 4];
            Bs[c4*4+0][r] = v.x;
            Bs[c4*4+1][r] = v.y;
            Bs[c4*4+2][r] = v.z;
            Bs[c4*4+3][r] = v.w;
        }
        __syncthreads();

        #pragma unroll
        for (int k = 0; k < BK; k++) {
            // 4 packed m-pairs, straight from shared (already adjacent in m)
            ulonglong2 a01 = *(const ulonglong2*)&As[k][ty * 8];
            ulonglong2 a23 = *(const ulonglong2*)&As[k][ty * 8 + 4];
            u64 am[4] = { a01.x, a01.y, a23.x, a23.y };
            float4 bv = *(const float4*)&Bs[k][tx * 4];
            u64 bd[4] = { pack2(bv.x, bv.x), pack2(bv.y, bv.y),
                          pack2(bv.z, bv.z), pack2(bv.w, bv.w) };
            #pragma unroll
            for (int i = 0; i < 4; i++)
                #pragma unroll
                for (int j = 0; j < 4; j++)
                    acc[i][j] = ffma2(am[i], bd[j], acc[i][j]);
        }
        __syncthreads();
    }

    #pragma unroll
    for (int i = 0; i < 4; i++) {
        float lo[4], hi[4];
        #pragma unroll
        for (int j = 0; j < 4; j++) unpack2(acc[i][j], lo[j], hi[j]);
        int r0 = m0 + ty * 8 + 2 * i;
        *(float4*)&Out[(size_t)r0 * D_ + tx * 4]       = make_float4(lo[0], lo[1], lo[2], lo[3]);
        *(float4*)&Out[(size_t)(r0 + 1) * D_ + tx * 4] = make_float4(hi[0], hi[1], hi[2], hi[3]);
    }
}

// ---------------------------------------------------------------------------
// K2: energy partials.  epart[b][s][d][e] = sum over this split's n of K*V
// grid (SPLITS, B), 256 threads, each thread 4x4 of the 64x64 output.
// ---------------------------------------------------------------------------
__global__ __launch_bounds__(256) void energy_kernel()
{
    const int s = blockIdx.x;
    const int b = blockIdx.y;
    const float* Kb = g_K + (size_t)b * N_ * D_;
    const float* Vb = g_V + (size_t)b * N_ * D_;
    const int n_base = s * ROWS_PER_SPLIT;

    __shared__ float Ks[16][D_];
    __shared__ float Vs[16][D_];

    const int tid = threadIdx.x;
    const int ty  = tid >> 4;
    const int tx  = tid & 15;

    u64 acc[4][2];   // [d-row][e-pair]  (pairs along e)
    #pragma unroll
    for (int i = 0; i < 4; i++) { acc[i][0] = 0ull; acc[i][1] = 0ull; }

    for (int c = 0; c < ROWS_PER_SPLIT; c += 16) {
        int r  = tid >> 4;
        int c4 = tid & 15;
        *(float4*)&Ks[r][c4 * 4] = *(const float4*)&Kb[(size_t)(n_base + c + r) * D_ + c4 * 4];
        *(float4*)&Vs[r][c4 * 4] = *(const float4*)&Vb[(size_t)(n_base + c + r) * D_ + c4 * 4];
        __syncthreads();
        #pragma unroll
        for (int n = 0; n < 16; n++) {
            float4 kv = *(const float4*)&Ks[n][ty * 4];
            ulonglong2 vv = *(const ulonglong2*)&Vs[n][tx * 4];
            u64 kd[4] = { pack2(kv.x, kv.x), pack2(kv.y, kv.y),
                          pack2(kv.z, kv.z), pack2(kv.w, kv.w) };
            #pragma unroll
            for (int i = 0; i < 4; i++) {
                acc[i][0] = ffma2(kd[i], vv.x, acc[i][0]);
                acc[i][1] = ffma2(kd[i], vv.y, acc[i][1]);
            }
        }
        __syncthreads();
    }

    float* ep = g_epart + ((size_t)(b * SPLITS + s)) * (D_ * D_);
    #pragma unroll
    for (int i = 0; i < 4; i++) {
        float e0, e1, e2, e3;
        unpack2(acc[i][0], e0, e1);
        unpack2(acc[i][1], e2, e3);
        *(float4*)&ep[(ty * 4 + i) * D_ + tx * 4] = make_float4(e0, e1, e2, e3);
    }
}

// ---------------------------------------------------------------------------
// K3: reduce partials + fold wo:  W2[b][d][e] = scale * sum_d2 energy[b][d][d2]*wo[e][d2]
// grid (D, B), 256 threads.
// ---------------------------------------------------------------------------
__global__ __launch_bounds__(256) void w2_kernel(const float* __restrict__ Wo)
{
    const int d = blockIdx.x;
    const int b = blockIdx.y;
    __shared__ float part[4][D_];
    __shared__ float row[D_];

    const int tid = threadIdx.x;
    const int d2  = tid & 63;
    const int sg  = tid >> 6;   // 0..3

    float sum = 0.f;
    for (int s = sg; s < SPLITS; s += 4)
        sum += g_epart[((size_t)(b * SPLITS + s)) * (D_ * D_) + d * D_ + d2];
    part[sg][d2] = sum;
    __syncthreads();
    if (tid < D_)
        row[tid] = (part[0][tid] + part[1][tid] + part[2][tid] + part[3][tid]) * SCALE_;
    __syncthreads();

    float* w2row = g_W2 + ((size_t)(b * D_ + d)) * E_;
    for (int e = tid; e < E_; e += 256) {
        const float4* wo4 = (const float4*)&Wo[(size_t)e * D_];
        float acc = 0.f;
        #pragma unroll
        for (int k4 = 0; k4 < D_ / 4; k4++) {
            float4 w = wo4[k4];
            acc += row[k4*4+0] * w.x + row[k4*4+1] * w.y
                 + row[k4*4+2] * w.z + row[k4*4+3] * w.w;
        }
        w2row[e] = acc;
    }
}

// ---------------------------------------------------------------------------
// K4: out[b][m][e] = sum_d Q[b][m][d] * W2[b][d][e]
// BM=64, BN=64, BK=64 (whole K), 256 threads.
// Microtile 4m x 4n per thread, computed as 4 m x 2 packed n-pairs (FFMA2).
// Ws[k][e] reads directly as packed pairs; Qs stays [m][k] (broadcast, no
// transpose, no bank conflicts).
// ---------------------------------------------------------------------------
__global__ __launch_bounds__(256) void out_kernel(float* __restrict__ Out)
{
    __shared__ float Qs[D_][D_];   // [m][k]
    __shared__ float Ws[D_][D_];   // [k][e]

    const int m0 = blockIdx.x * 64;
    const int e0 = blockIdx.y * 64;
    const int b  = blockIdx.z;
    const float* Qb  = g_Q  + (size_t)b * N_ * D_;
    const float* W2b = g_W2 + (size_t)b * D_ * E_;

    const int tid = threadIdx.x;
    #pragma unroll
    for (int i = 0; i < 4; i++) {
        int idx = i * 256 + tid;
        int r   = idx >> 4;
        int c4  = idx & 15;
        *(float4*)&Qs[r][c4 * 4] = *(const float4*)&Qb[(size_t)(m0 + r) * D_ + c4 * 4];
        *(float4*)&Ws[r][c4 * 4] = *(const float4*)&W2b[(size_t)r * E_ + e0 + c4 * 4];
    }
    __syncthreads();

    const int ty = tid >> 4;
    const int tx = tid & 15;
    u64 acc[4][2];   // [m][n-pair]
    #pragma unroll
    for (int i = 0; i < 4; i++) { acc[i][0] = 0ull; acc[i][1] = 0ull; }

    #pragma unroll
    for (int k = 0; k < D_; k++) {
        float a0 = Qs[ty*4+0][k];
        float a1 = Qs[ty*4+1][k];
        float a2 = Qs[ty*4+2][k];
        float a3 = Qs[ty*4+3][k];
        ulonglong2 bb = *(const ulonglong2*)&Ws[k][tx * 4];
        u64 ad[4] = { pack2(a0, a0), pack2(a1, a1), pack2(a2, a2), pack2(a3, a3) };
        #pragma unroll
        for (int i = 0; i < 4; i++) {
            acc[i][0] = ffma2(ad[i], bb.x, acc[i][0]);
            acc[i][1] = ffma2(ad[i], bb.y, acc[i][1]);
        }
    }

    #pragma unroll
    for (int i = 0; i < 4; i++) {
        float e0v, e1v, e2v, e3v;
        unpack2(acc[i][0], e0v, e1v);
        unpack2(acc[i][1], e2v, e3v);
        *(float4*)&Out[((size_t)b * N_ + m0 + ty * 4 + i) * E_ + e0 + tx * 4] =
            make_float4(e0v, e1v, e2v, e3v);
    }
}

// ---------------------------------------------------------------------------
extern "C" void kernel_launch(void* const* d_in, const int* in_sizes, int n_in,
                              void* d_out, int out_size)
{
    const float* x  = (const float*)d_in[0];
    const float* wq = (const float*)d_in[1];
    const float* wk = (const float*)d_in[2];
    const float* wv = (const float*)d_in[3];
    const float* wo = (const float*)d_in[4];
    float* out = (float*)d_out;

    qkv_kernel   <<<dim3(M_ / 128, 3), 256>>>(x, wq, wk, wv);
    energy_kernel<<<dim3(SPLITS, B_), 256>>>();
    w2_kernel    <<<dim3(D_, B_), 256>>>(wo);
    out_kernel   <<<dim3(N_ / 64, E_ / 64, B_), 256>>>(out);
}

// round 3
// speedup vs baseline: 1.0617x; 1.0364x over previous
#include <cuda_runtime.h>

#define B_ 4
#define N_ 8192
#define E_ 1024
#define D_ 64
#define M_ (B_*N_)          // 32768 rows of X
#define SPLITS 64
#define ROWS_PER_SPLIT (N_/SPLITS)   // 128
#define SCALE_ 0.21650635094610965f  // sqrt(3/64)

using u64 = unsigned long long;

// Packed f32x2 helpers (sm_100+). fma.rn.f32x2 = 2 IEEE fp32 FMAs in one inst.
__device__ __forceinline__ u64 pack2(float lo, float hi) {
    u64 r; asm("mov.b64 %0, {%1, %2};" : "=l"(r) : "f"(lo), "f"(hi)); return r;
}
__device__ __forceinline__ void unpack2(u64 v, float& lo, float& hi) {
    asm("mov.b64 {%0, %1}, %2;" : "=f"(lo), "=f"(hi) : "l"(v));
}
__device__ __forceinline__ u64 ffma2(u64 a, u64 b, u64 c) {
    u64 d; asm("fma.rn.f32x2 %0, %1, %2, %3;" : "=l"(d) : "l"(a), "l"(b), "l"(c)); return d;
}

// Scratch (device globals; no allocation allowed)
__device__ float g_Q[M_*D_];
__device__ float g_K[M_*D_];
__device__ float g_V[M_*D_];
__device__ float g_epart[B_*SPLITS*D_*D_];
__device__ float g_W2[B_*D_*E_];

// ---------------------------------------------------------------------------
// K1: QKV projection.  Out[m][d] = sum_e X[m][e] * W[d][e]
// BM=128, BN=64(=D), BK=16, 128 threads. Microtile 8m x 8n per thread:
// 4 packed m-pairs (straight f32x2 loads from As) x 8 n (dup-packed).
// Per k: 64B LDS / 128 FLOP -> FMA-bound, not crossbar-bound.
// ---------------------------------------------------------------------------
__global__ __launch_bounds__(128) void qkv_kernel(
    const float* __restrict__ X,
    const float* __restrict__ Wq,
    const float* __restrict__ Wk,
    const float* __restrict__ Wv)
{
    constexpr int BM = 128, BK = 16;
    __shared__ float As[BK][BM + 4];   // [k][m], padded vs transpose-store conflicts
    __shared__ float Bs[BK][D_ + 4];   // [k][n]

    const float* W   = (blockIdx.y == 0) ? Wq : (blockIdx.y == 1 ? Wk : Wv);
    float*       Out = (blockIdx.y == 0) ? g_Q : (blockIdx.y == 1 ? g_K : g_V);

    const int m0  = blockIdx.x * BM;
    const int tid = threadIdx.x;
    const int ty  = tid >> 3;   // 0..15 -> m group of 8
    const int tx  = tid & 7;    // 0..7  -> n group of 8

    u64 acc[4][8];               // [m-pair][n]
    #pragma unroll
    for (int i = 0; i < 4; i++)
        #pragma unroll
        for (int j = 0; j < 8; j++) acc[i][j] = 0ull;

    for (int k0 = 0; k0 < E_; k0 += BK) {
        // Load X tile 128x16, transposed into As. 512 float4, 4 per thread.
        #pragma unroll
        for (int t = 0; t < 4; t++) {
            int idx = t * 128 + tid;
            int r   = idx >> 2;
            int c4  = idx & 3;
            float4 v = *(const float4*)&X[(size_t)(m0 + r) * E_ + k0 + c4 * 4];
            As[c4*4+0][r] = v.x;
            As[c4*4+1][r] = v.y;
            As[c4*4+2][r] = v.z;
            As[c4*4+3][r] = v.w;
        }
        // Load W tile 64x16, transposed into Bs. 256 float4, 2 per thread.
        #pragma unroll
        for (int t = 0; t < 2; t++) {
            int idx = t * 128 + tid;
            int r   = idx >> 2;
            int c4  = idx & 3;
            float4 v = *(const float4*)&W[(size_t)r * E_ + k0 + c4 * 4];
            Bs[c4*4+0][r] = v.x;
            Bs[c4*4+1][r] = v.y;
            Bs[c4*4+2][r] = v.z;
            Bs[c4*4+3][r] = v.w;
        }
        __syncthreads();

        #pragma unroll
        for (int k = 0; k < BK; k++) {
            ulonglong2 a01 = *(const ulonglong2*)&As[k][ty * 8];
            ulonglong2 a23 = *(const ulonglong2*)&As[k][ty * 8 + 4];
            u64 am[4] = { a01.x, a01.y, a23.x, a23.y };
            float4 b0 = *(const float4*)&Bs[k][tx * 8];
            float4 b1 = *(const float4*)&Bs[k][tx * 8 + 4];
            u64 bd[8] = { pack2(b0.x, b0.x), pack2(b0.y, b0.y),
                          pack2(b0.z, b0.z), pack2(b0.w, b0.w),
                          pack2(b1.x, b1.x), pack2(b1.y, b1.y),
                          pack2(b1.z, b1.z), pack2(b1.w, b1.w) };
            #pragma unroll
            for (int i = 0; i < 4; i++)
                #pragma unroll
                for (int j = 0; j < 8; j++)
                    acc[i][j] = ffma2(am[i], bd[j], acc[i][j]);
        }
        __syncthreads();
    }

    #pragma unroll
    for (int i = 0; i < 4; i++) {
        float lo[8], hi[8];
        #pragma unroll
        for (int j = 0; j < 8; j++) unpack2(acc[i][j], lo[j], hi[j]);
        int r0 = m0 + ty * 8 + 2 * i;
        *(float4*)&Out[(size_t)r0 * D_ + tx * 8]           = make_float4(lo[0], lo[1], lo[2], lo[3]);
        *(float4*)&Out[(size_t)r0 * D_ + tx * 8 + 4]       = make_float4(lo[4], lo[5], lo[6], lo[7]);
        *(float4*)&Out[(size_t)(r0 + 1) * D_ + tx * 8]     = make_float4(hi[0], hi[1], hi[2], hi[3]);
        *(float4*)&Out[(size_t)(r0 + 1) * D_ + tx * 8 + 4] = make_float4(hi[4], hi[5], hi[6], hi[7]);
    }
}

// ---------------------------------------------------------------------------
// K2: energy partials.  epart[b][s][d][e] = sum over this split's n of K*V
// grid (SPLITS, B), 256 threads, each thread 4x4 of the 64x64 output.
// ---------------------------------------------------------------------------
__global__ __launch_bounds__(256) void energy_kernel()
{
    const int s = blockIdx.x;
    const int b = blockIdx.y;
    const float* Kb = g_K + (size_t)b * N_ * D_;
    const float* Vb = g_V + (size_t)b * N_ * D_;
    const int n_base = s * ROWS_PER_SPLIT;

    __shared__ float Ks[16][D_];
    __shared__ float Vs[16][D_];

    const int tid = threadIdx.x;
    const int ty  = tid >> 4;
    const int tx  = tid & 15;

    u64 acc[4][2];   // [d-row][e-pair]
    #pragma unroll
    for (int i = 0; i < 4; i++) { acc[i][0] = 0ull; acc[i][1] = 0ull; }

    for (int c = 0; c < ROWS_PER_SPLIT; c += 16) {
        int r  = tid >> 4;
        int c4 = tid & 15;
        *(float4*)&Ks[r][c4 * 4] = *(const float4*)&Kb[(size_t)(n_base + c + r) * D_ + c4 * 4];
        *(float4*)&Vs[r][c4 * 4] = *(const float4*)&Vb[(size_t)(n_base + c + r) * D_ + c4 * 4];
        __syncthreads();
        #pragma unroll
        for (int n = 0; n < 16; n++) {
            float4 kv = *(const float4*)&Ks[n][ty * 4];
            ulonglong2 vv = *(const ulonglong2*)&Vs[n][tx * 4];
            u64 kd[4] = { pack2(kv.x, kv.x), pack2(kv.y, kv.y),
                          pack2(kv.z, kv.z), pack2(kv.w, kv.w) };
            #pragma unroll
            for (int i = 0; i < 4; i++) {
                acc[i][0] = ffma2(kd[i], vv.x, acc[i][0]);
                acc[i][1] = ffma2(kd[i], vv.y, acc[i][1]);
            }
        }
        __syncthreads();
    }

    float* ep = g_epart + ((size_t)(b * SPLITS + s)) * (D_ * D_);
    #pragma unroll
    for (int i = 0; i < 4; i++) {
        float e0, e1, e2, e3;
        unpack2(acc[i][0], e0, e1);
        unpack2(acc[i][1], e2, e3);
        *(float4*)&ep[(ty * 4 + i) * D_ + tx * 4] = make_float4(e0, e1, e2, e3);
    }
}

// ---------------------------------------------------------------------------
// K3: reduce partials + fold wo:  W2[b][d][e] = scale * sum_d2 energy[b][d][d2]*wo[e][d2]
// ---------------------------------------------------------------------------
__global__ __launch_bounds__(256) void w2_kernel(const float* __restrict__ Wo)
{
    const int d = blockIdx.x;
    const int b = blockIdx.y;
    __shared__ float part[4][D_];
    __shared__ float row[D_];

    const int tid = threadIdx.x;
    const int d2  = tid & 63;
    const int sg  = tid >> 6;

    float sum = 0.f;
    for (int s = sg; s < SPLITS; s += 4)
        sum += g_epart[((size_t)(b * SPLITS + s)) * (D_ * D_) + d * D_ + d2];
    part[sg][d2] = sum;
    __syncthreads();
    if (tid < D_)
        row[tid] = (part[0][tid] + part[1][tid] + part[2][tid] + part[3][tid]) * SCALE_;
    __syncthreads();

    float* w2row = g_W2 + ((size_t)(b * D_ + d)) * E_;
    for (int e = tid; e < E_; e += 256) {
        const float4* wo4 = (const float4*)&Wo[(size_t)e * D_];
        float acc = 0.f;
        #pragma unroll
        for (int k4 = 0; k4 < D_ / 4; k4++) {
            float4 w = wo4[k4];
            acc += row[k4*4+0] * w.x + row[k4*4+1] * w.y
                 + row[k4*4+2] * w.z + row[k4*4+3] * w.w;
        }
        w2row[e] = acc;
    }
}

// ---------------------------------------------------------------------------
// K4: out[b][m][e] = sum_d Q[b][m][d] * W2[b][d][e]
// BM=64, BN=128, BK=32 (two chunks), 128 threads. Microtile 8m x 8n:
// 4 packed m-pairs from transposed Qs x 8 n (dup-packed) -> FMA-bound.
// ---------------------------------------------------------------------------
__global__ __launch_bounds__(128) void out_kernel(float* __restrict__ Out)
{
    constexpr int BN = 128, BK = 32;
    __shared__ float Qs[BK][D_ + 4];   // [k][m], transposed, padded
    __shared__ float Ws[BK][BN];       // [k][e], natural

    const int m0 = blockIdx.x * 64;
    const int e0 = blockIdx.y * BN;
    const int b  = blockIdx.z;
    const float* Qb  = g_Q  + (size_t)b * N_ * D_;
    const float* W2b = g_W2 + (size_t)b * D_ * E_;

    const int tid = threadIdx.x;
    const int ty  = tid >> 4;   // 0..7  -> m group of 8
    const int tx  = tid & 15;   // 0..15 -> n group of 8

    u64 acc[4][8];   // [m-pair][n]
    #pragma unroll
    for (int i = 0; i < 4; i++)
        #pragma unroll
        for (int j = 0; j < 8; j++) acc[i][j] = 0ull;

    for (int k0 = 0; k0 < D_; k0 += BK) {
        // Q tile 64m x 32k, transposed into Qs. 512 float4, 4 per thread.
        #pragma unroll
        for (int t = 0; t < 4; t++) {
            int idx = t * 128 + tid;
            int m   = idx >> 3;        // 0..63
            int c4  = idx & 7;         // 0..7 -> k chunk of 4
            float4 v = *(const float4*)&Qb[(size_t)(m0 + m) * D_ + k0 + c4 * 4];
            Qs[c4*4+0][m] = v.x;
            Qs[c4*4+1][m] = v.y;
            Qs[c4*4+2][m] = v.z;
            Qs[c4*4+3][m] = v.w;
        }
        // W2 tile 32k x 128e, natural. 1024 float4, 8 per thread.
        #pragma unroll
        for (int t = 0; t < 8; t++) {
            int idx = t * 128 + tid;
            int r   = idx >> 5;        // 0..31
            int c4  = idx & 31;        // 0..31
            *(float4*)&Ws[r][c4 * 4] =
                *(const float4*)&W2b[(size_t)(k0 + r) * E_ + e0 + c4 * 4];
        }
        __syncthreads();

        #pragma unroll 16
        for (int k = 0; k < BK; k++) {
            ulonglong2 a01 = *(const ulonglong2*)&Qs[k][ty * 8];
            ulonglong2 a23 = *(const ulonglong2*)&Qs[k][ty * 8 + 4];
            u64 am[4] = { a01.x, a01.y, a23.x, a23.y };
            float4 b0 = *(const float4*)&Ws[k][tx * 8];
            float4 b1 = *(const float4*)&Ws[k][tx * 8 + 4];
            u64 bd[8] = { pack2(b0.x, b0.x), pack2(b0.y, b0.y),
                          pack2(b0.z, b0.z), pack2(b0.w, b0.w),
                          pack2(b1.x, b1.x), pack2(b1.y, b1.y),
                          pack2(b1.z, b1.z), pack2(b1.w, b1.w) };
            #pragma unroll
            for (int i = 0; i < 4; i++)
                #pragma unroll
                for (int j = 0; j < 8; j++)
                    acc[i][j] = ffma2(am[i], bd[j], acc[i][j]);
        }
        __syncthreads();
    }

    #pragma unroll
    for (int i = 0; i < 4; i++) {
        float lo[8], hi[8];
        #pragma unroll
        for (int j = 0; j < 8; j++) unpack2(acc[i][j], lo[j], hi[j]);
        int r0 = m0 + ty * 8 + 2 * i;
        size_t base0 = ((size_t)b * N_ + r0) * E_ + e0 + tx * 8;
        size_t base1 = ((size_t)b * N_ + r0 + 1) * E_ + e0 + tx * 8;
        *(float4*)&Out[base0]     = make_float4(lo[0], lo[1], lo[2], lo[3]);
        *(float4*)&Out[base0 + 4] = make_float4(lo[4], lo[5], lo[6], lo[7]);
        *(float4*)&Out[base1]     = make_float4(hi[0], hi[1], hi[2], hi[3]);
        *(float4*)&Out[base1 + 4] = make_float4(hi[4], hi[5], hi[6], hi[7]);
    }
}

// ---------------------------------------------------------------------------
extern "C" void kernel_launch(void* const* d_in, const int* in_sizes, int n_in,
                              void* d_out, int out_size)
{
    const float* x  = (const float*)d_in[0];
    const float* wq = (const float*)d_in[1];
    const float* wk = (const float*)d_in[2];
    const float* wv = (const float*)d_in[3];
    const float* wo = (const float*)d_in[4];
    float* out = (float*)d_out;

    qkv_kernel   <<<dim3(M_ / 128, 3), 128>>>(x, wq, wk, wv);
    energy_kernel<<<dim3(SPLITS, B_), 256>>>();
    w2_kernel    <<<dim3(D_, B_), 256>>>(wo);
    out_kernel   <<<dim3(N_ / 64, E_ / 128, B_), 128>>>(out);
}

// round 4
// speedup vs baseline: 2.0254x; 1.9077x over previous
#include <cuda_runtime.h>
#include <cuda_bf16.h>

#define B_ 4
#define N_ 8192
#define E_ 1024
#define D_ 64
#define M_ (B_*N_)          // 32768 rows of X
#define SPLITS 64
#define ROWS_PER_SPLIT (N_/SPLITS)   // 128
#define SCALE_ 0.21650635094610965f  // sqrt(3/64)

// Scratch (device globals; no allocation allowed)
__device__ float g_K[M_*D_];
__device__ float g_V[M_*D_];
__device__ float g_epart[B_*SPLITS*D_*D_];
__device__ __nv_bfloat16 g_Qhi[M_*D_];
__device__ __nv_bfloat16 g_Qlo[M_*D_];
__device__ __nv_bfloat16 g_W2thi[B_*E_*D_];   // [b][e][d] transposed for B-frag
__device__ __nv_bfloat16 g_W2tlo[B_*E_*D_];

// ---------------------------------------------------------------------------
// helpers
// ---------------------------------------------------------------------------
__device__ __forceinline__ void split2(float x, __nv_bfloat16& h, __nv_bfloat16& l) {
    h = __float2bfloat16_rn(x);
    l = __float2bfloat16_rn(x - __bfloat162float(h));
}

// D(16x8,f32) += A(16x16,bf16,row) * B(16x8,bf16,col)
__device__ __forceinline__ void mma16816(float* d, const unsigned* a, const unsigned* b) {
    asm volatile(
        "mma.sync.aligned.m16n8k16.row.col.f32.bf16.bf16.f32 "
        "{%0,%1,%2,%3}, {%4,%5,%6,%7}, {%8,%9}, {%0,%1,%2,%3};\n"
        : "+f"(d[0]), "+f"(d[1]), "+f"(d[2]), "+f"(d[3])
        : "r"(a[0]), "r"(a[1]), "r"(a[2]), "r"(a[3]), "r"(b[0]), "r"(b[1]));
}

// ---------------------------------------------------------------------------
// K1: QKV projection on tensor cores.
// Out[m][d] = sum_e X[m][e]*W[d][e].  X split into bf16 hi/lo; W exact bf16
// (values are +-2^-5).  CTA 256 thr = 8 warps (4m x 2n), BM=128, BN=64, BK=32.
// Warp tile 32m x 32n: (2 m16)x(4 n8) frags, 2 products (Xhi,Xlo) per k16.
// y==0 writes Q as bf16 hi/lo; y==1/2 write K/V fp32 for the energy path.
// ---------------------------------------------------------------------------
__global__ __launch_bounds__(256) void qkv_mma_kernel(
    const float* __restrict__ X,
    const float* __restrict__ Wq,
    const float* __restrict__ Wk,
    const float* __restrict__ Wv)
{
    __shared__ __nv_bfloat16 Xh[128][40];   // [m][k], pad 8 -> conflict-free frags
    __shared__ __nv_bfloat16 Xl[128][40];
    __shared__ __nv_bfloat16 Wb[64][40];    // [n][k]

    const int y = blockIdx.y;
    const float* W = (y == 0) ? Wq : (y == 1 ? Wk : Wv);
    const int m0   = blockIdx.x * 128;
    const int tid  = threadIdx.x;
    const int warp = tid >> 5, lane = tid & 31;
    const int wm = warp >> 1, wn = warp & 1;
    const int lr = lane >> 2;          // fragment row/col group
    const int lc = (lane & 3) * 2;     // fragment k offset

    float acc[2][4][4];
    #pragma unroll
    for (int i = 0; i < 2; i++)
        #pragma unroll
        for (int j = 0; j < 4; j++)
            #pragma unroll
            for (int q = 0; q < 4; q++) acc[i][j][q] = 0.f;

    for (int k0 = 0; k0 < E_; k0 += 32) {
        // X tile 128x32 fp32 -> split into Xh/Xl.  1024 float4, 4/thread.
        #pragma unroll
        for (int t = 0; t < 4; t++) {
            int idx = t * 256 + tid;
            int r = idx >> 3, c4 = idx & 7;
            float4 v = *(const float4*)&X[(size_t)(m0 + r) * E_ + k0 + c4 * 4];
            __nv_bfloat16 h0,l0,h1,l1,h2,l2,h3,l3;
            split2(v.x, h0, l0); split2(v.y, h1, l1);
            split2(v.z, h2, l2); split2(v.w, h3, l3);
            *(__nv_bfloat162*)&Xh[r][c4*4]     = __halves2bfloat162(h0, h1);
            *(__nv_bfloat162*)&Xh[r][c4*4 + 2] = __halves2bfloat162(h2, h3);
            *(__nv_bfloat162*)&Xl[r][c4*4]     = __halves2bfloat162(l0, l1);
            *(__nv_bfloat162*)&Xl[r][c4*4 + 2] = __halves2bfloat162(l2, l3);
        }
        // W tile 64x32 fp32 -> bf16 (exact).  512 float4, 2/thread.
        #pragma unroll
        for (int t = 0; t < 2; t++) {
            int idx = t * 256 + tid;
            int r = idx >> 3, c4 = idx & 7;
            float4 v = *(const float4*)&W[(size_t)r * E_ + k0 + c4 * 4];
            *(__nv_bfloat162*)&Wb[r][c4*4]     =
                __halves2bfloat162(__float2bfloat16_rn(v.x), __float2bfloat16_rn(v.y));
            *(__nv_bfloat162*)&Wb[r][c4*4 + 2] =
                __halves2bfloat162(__float2bfloat16_rn(v.z), __float2bfloat16_rn(v.w));
        }
        __syncthreads();

        #pragma unroll
        for (int ks = 0; ks < 32; ks += 16) {
            unsigned bf[4][2];
            #pragma unroll
            for (int nt = 0; nt < 4; nt++) {
                int n = wn * 32 + nt * 8 + lr;
                bf[nt][0] = *(const unsigned*)&Wb[n][ks + lc];
                bf[nt][1] = *(const unsigned*)&Wb[n][ks + lc + 8];
            }
            #pragma unroll
            for (int mt = 0; mt < 2; mt++) {
                int r0 = wm * 32 + mt * 16 + lr;
                int c  = ks + lc;
                unsigned ah[4], al[4];
                ah[0] = *(const unsigned*)&Xh[r0][c];
                ah[1] = *(const unsigned*)&Xh[r0 + 8][c];
                ah[2] = *(const unsigned*)&Xh[r0][c + 8];
                ah[3] = *(const unsigned*)&Xh[r0 + 8][c + 8];
                al[0] = *(const unsigned*)&Xl[r0][c];
                al[1] = *(const unsigned*)&Xl[r0 + 8][c];
                al[2] = *(const unsigned*)&Xl[r0][c + 8];
                al[3] = *(const unsigned*)&Xl[r0 + 8][c + 8];
                #pragma unroll
                for (int nt = 0; nt < 4; nt++) mma16816(acc[mt][nt], ah, bf[nt]);
                #pragma unroll
                for (int nt = 0; nt < 4; nt++) mma16816(acc[mt][nt], al, bf[nt]);
            }
        }
        __syncthreads();
    }

    // Epilogue
    if (y == 0) {
        #pragma unroll
        for (int mt = 0; mt < 2; mt++)
            #pragma unroll
            for (int nt = 0; nt < 4; nt++) {
                int row = m0 + wm * 32 + mt * 16 + lr;
                int col = wn * 32 + nt * 8 + lc;
                __nv_bfloat16 h0,l0,h1,l1;
                split2(acc[mt][nt][0], h0, l0); split2(acc[mt][nt][1], h1, l1);
                *(__nv_bfloat162*)&g_Qhi[(size_t)row * D_ + col] = __halves2bfloat162(h0, h1);
                *(__nv_bfloat162*)&g_Qlo[(size_t)row * D_ + col] = __halves2bfloat162(l0, l1);
                split2(acc[mt][nt][2], h0, l0); split2(acc[mt][nt][3], h1, l1);
                *(__nv_bfloat162*)&g_Qhi[(size_t)(row + 8) * D_ + col] = __halves2bfloat162(h0, h1);
                *(__nv_bfloat162*)&g_Qlo[(size_t)(row + 8) * D_ + col] = __halves2bfloat162(l0, l1);
            }
    } else {
        float* Out = (y == 1) ? g_K : g_V;
        #pragma unroll
        for (int mt = 0; mt < 2; mt++)
            #pragma unroll
            for (int nt = 0; nt < 4; nt++) {
                int row = m0 + wm * 32 + mt * 16 + lr;
                int col = wn * 32 + nt * 8 + lc;
                *(float2*)&Out[(size_t)row * D_ + col] =
                    make_float2(acc[mt][nt][0], acc[mt][nt][1]);
                *(float2*)&Out[(size_t)(row + 8) * D_ + col] =
                    make_float2(acc[mt][nt][2], acc[mt][nt][3]);
            }
    }
}

// ---------------------------------------------------------------------------
// K2: energy partials (fp32 SIMT, unchanged).
// ---------------------------------------------------------------------------
__global__ __launch_bounds__(256) void energy_kernel()
{
    const int s = blockIdx.x;
    const int b = blockIdx.y;
    const float* Kb = g_K + (size_t)b * N_ * D_;
    const float* Vb = g_V + (size_t)b * N_ * D_;
    const int n_base = s * ROWS_PER_SPLIT;

    __shared__ float Ks[16][D_];
    __shared__ float Vs[16][D_];

    const int tid = threadIdx.x;
    const int ty  = tid >> 4;
    const int tx  = tid & 15;

    float acc[4][4];
    #pragma unroll
    for (int i = 0; i < 4; i++)
        #pragma unroll
        for (int j = 0; j < 4; j++) acc[i][j] = 0.f;

    for (int c = 0; c < ROWS_PER_SPLIT; c += 16) {
        int r  = tid >> 4;
        int c4 = tid & 15;
        *(float4*)&Ks[r][c4 * 4] = *(const float4*)&Kb[(size_t)(n_base + c + r) * D_ + c4 * 4];
        *(float4*)&Vs[r][c4 * 4] = *(const float4*)&Vb[(size_t)(n_base + c + r) * D_ + c4 * 4];
        __syncthreads();
        #pragma unroll
        for (int n = 0; n < 16; n++) {
            float kv[4], vv[4];
            *(float4*)&kv[0] = *(const float4*)&Ks[n][ty * 4];
            *(float4*)&vv[0] = *(const float4*)&Vs[n][tx * 4];
            #pragma unroll
            for (int i = 0; i < 4; i++)
                #pragma unroll
                for (int j = 0; j < 4; j++)
                    acc[i][j] += kv[i] * vv[j];
        }
        __syncthreads();
    }

    float* ep = g_epart + ((size_t)(b * SPLITS + s)) * (D_ * D_);
    #pragma unroll
    for (int i = 0; i < 4; i++)
        *(float4*)&ep[(ty * 4 + i) * D_ + tx * 4] =
            make_float4(acc[i][0], acc[i][1], acc[i][2], acc[i][3]);
}

// ---------------------------------------------------------------------------
// K3: reduce partials + fold wo; emit W2^T (=[e][d]) as bf16 hi/lo.
// ---------------------------------------------------------------------------
__global__ __launch_bounds__(256) void w2_kernel(const float* __restrict__ Wo)
{
    const int d = blockIdx.x;
    const int b = blockIdx.y;
    __shared__ float part[4][D_];
    __shared__ float row[D_];

    const int tid = threadIdx.x;
    const int d2  = tid & 63;
    const int sg  = tid >> 6;

    float sum = 0.f;
    for (int s = sg; s < SPLITS; s += 4)
        sum += g_epart[((size_t)(b * SPLITS + s)) * (D_ * D_) + d * D_ + d2];
    part[sg][d2] = sum;
    __syncthreads();
    if (tid < D_)
        row[tid] = (part[0][tid] + part[1][tid] + part[2][tid] + part[3][tid]) * SCALE_;
    __syncthreads();

    for (int e = tid; e < E_; e += 256) {
        const float4* wo4 = (const float4*)&Wo[(size_t)e * D_];
        float acc = 0.f;
        #pragma unroll
        for (int k4 = 0; k4 < D_ / 4; k4++) {
            float4 w = wo4[k4];
            acc += row[k4*4+0] * w.x + row[k4*4+1] * w.y
                 + row[k4*4+2] * w.z + row[k4*4+3] * w.w;
        }
        __nv_bfloat16 h, l;
        split2(acc, h, l);
        size_t idx = ((size_t)b * E_ + e) * D_ + d;
        g_W2thi[idx] = h;
        g_W2tlo[idx] = l;
    }
}

// ---------------------------------------------------------------------------
// K4: out[b][m][e] = sum_d Q[b][m][d] * W2[b][d][e] on tensor cores.
// 3-product bf16 split: Qh*Wh + Qh*Wl + Ql*Wh.
// CTA 256 thr = 8 warps (4m x 2n), BM=128, BN=64, BK=32 (2 chunks of K=64).
// ---------------------------------------------------------------------------
__global__ __launch_bounds__(256) void out_mma_kernel(float* __restrict__ Out)
{
    __shared__ __nv_bfloat16 Qh[128][40];
    __shared__ __nv_bfloat16 Ql[128][40];
    __shared__ __nv_bfloat16 Wh[64][40];
    __shared__ __nv_bfloat16 Wl[64][40];

    const int m0 = blockIdx.x * 128;
    const int e0 = blockIdx.y * 64;
    const int b  = blockIdx.z;
    const int tid  = threadIdx.x;
    const int warp = tid >> 5, lane = tid & 31;
    const int wm = warp >> 1, wn = warp & 1;
    const int lr = lane >> 2;
    const int lc = (lane & 3) * 2;

    const size_t qbase = ((size_t)b * N_ + m0) * D_;
    const size_t wbase = ((size_t)b * E_ + e0) * D_;

    float acc[2][4][4];
    #pragma unroll
    for (int i = 0; i < 2; i++)
        #pragma unroll
        for (int j = 0; j < 4; j++)
            #pragma unroll
            for (int q = 0; q < 4; q++) acc[i][j][q] = 0.f;

    for (int k0 = 0; k0 < D_; k0 += 32) {
        // Q tiles 128x32 bf16 (hi & lo): 1024 uint2 each, 4/thread.
        #pragma unroll
        for (int t = 0; t < 4; t++) {
            int idx = t * 256 + tid;
            int r = idx >> 3, c4 = idx & 7;
            *(uint2*)&Qh[r][c4*4] = *(const uint2*)&g_Qhi[qbase + (size_t)r * D_ + k0 + c4 * 4];
            *(uint2*)&Ql[r][c4*4] = *(const uint2*)&g_Qlo[qbase + (size_t)r * D_ + k0 + c4 * 4];
        }
        // W2t tiles 64x32 bf16 (hi & lo): 512 uint2 each, 2/thread.
        #pragma unroll
        for (int t = 0; t < 2; t++) {
            int idx = t * 256 + tid;
            int r = idx >> 3, c4 = idx & 7;
            *(uint2*)&Wh[r][c4*4] = *(const uint2*)&g_W2thi[wbase + (size_t)r * D_ + k0 + c4 * 4];
            *(uint2*)&Wl[r][c4*4] = *(const uint2*)&g_W2tlo[wbase + (size_t)r * D_ + k0 + c4 * 4];
        }
        __syncthreads();

        #pragma unroll
        for (int ks = 0; ks < 32; ks += 16) {
            unsigned bh[4][2], bl[4][2];
            #pragma unroll
            for (int nt = 0; nt < 4; nt++) {
                int n = wn * 32 + nt * 8 + lr;
                bh[nt][0] = *(const unsigned*)&Wh[n][ks + lc];
                bh[nt][1] = *(const unsigned*)&Wh[n][ks + lc + 8];
                bl[nt][0] = *(const unsigned*)&Wl[n][ks + lc];
                bl[nt][1] = *(const unsigned*)&Wl[n][ks + lc + 8];
            }
            #pragma unroll
            for (int mt = 0; mt < 2; mt++) {
                int r0 = wm * 32 + mt * 16 + lr;
                int c  = ks + lc;
                unsigned ah[4], al[4];
                ah[0] = *(const unsigned*)&Qh[r0][c];
                ah[1] = *(const unsigned*)&Qh[r0 + 8][c];
                ah[2] = *(const unsigned*)&Qh[r0][c + 8];
                ah[3] = *(const unsigned*)&Qh[r0 + 8][c + 8];
                al[0] = *(const unsigned*)&Ql[r0][c];
                al[1] = *(const unsigned*)&Ql[r0 + 8][c];
                al[2] = *(const unsigned*)&Ql[r0][c + 8];
                al[3] = *(const unsigned*)&Ql[r0 + 8][c + 8];
                #pragma unroll
                for (int nt = 0; nt < 4; nt++) mma16816(acc[mt][nt], ah, bh[nt]);
                #pragma unroll
                for (int nt = 0; nt < 4; nt++) mma16816(acc[mt][nt], ah, bl[nt]);
                #pragma unroll
                for (int nt = 0; nt < 4; nt++) mma16816(acc[mt][nt], al, bh[nt]);
            }
        }
        __syncthreads();
    }

    #pragma unroll
    for (int mt = 0; mt < 2; mt++)
        #pragma unroll
        for (int nt = 0; nt < 4; nt++) {
            int row = m0 + wm * 32 + mt * 16 + lr;
            int col = e0 + wn * 32 + nt * 8 + lc;
            *(float2*)&Out[((size_t)b * N_ + row) * E_ + col] =
                make_float2(acc[mt][nt][0], acc[mt][nt][1]);
            *(float2*)&Out[((size_t)b * N_ + row + 8) * E_ + col] =
                make_float2(acc[mt][nt][2], acc[mt][nt][3]);
        }
}

// ---------------------------------------------------------------------------
extern "C" void kernel_launch(void* const* d_in, const int* in_sizes, int n_in,
                              void* d_out, int out_size)
{
    const float* x  = (const float*)d_in[0];
    const float* wq = (const float*)d_in[1];
    const float* wk = (const float*)d_in[2];
    const float* wv = (const float*)d_in[3];
    const float* wo = (const float*)d_in[4];
    float* out = (float*)d_out;

    qkv_mma_kernel<<<dim3(M_ / 128, 3), 256>>>(x, wq, wk, wv);
    energy_kernel <<<dim3(SPLITS, B_), 256>>>();
    w2_kernel     <<<dim3(D_, B_), 256>>>(wo);
    out_mma_kernel<<<dim3(N_ / 128, E_ / 64, B_), 256>>>(out);
}

// round 5
// speedup vs baseline: 2.2823x; 1.1268x over previous
#include <cuda_runtime.h>
#include <cuda_bf16.h>

#define B_ 4
#define N_ 8192
#define E_ 1024
#define D_ 64
#define M_ (B_*N_)          // 32768 rows of X
#define SPLITS 128
#define ROWS_PER_SPLIT (N_/SPLITS)   // 64
#define SCALE_ 0.21650635094610965f  // sqrt(3/64)

// Scratch (device globals; no allocation allowed)
__device__ float g_K[M_*D_];
__device__ float g_V[M_*D_];
__device__ float g_epart[B_*SPLITS*D_*D_];
__device__ __nv_bfloat16 g_Qhi[M_*D_];
__device__ __nv_bfloat16 g_Qlo[M_*D_];
__device__ __nv_bfloat16 g_W2thi[B_*E_*D_];   // [b][e][d] transposed for B-frag
__device__ __nv_bfloat16 g_W2tlo[B_*E_*D_];

// ---------------------------------------------------------------------------
// helpers
// ---------------------------------------------------------------------------
__device__ __forceinline__ void split2(float x, __nv_bfloat16& h, __nv_bfloat16& l) {
    h = __float2bfloat16_rn(x);
    l = __float2bfloat16_rn(x - __bfloat162float(h));
}

__device__ __forceinline__ uint2 split_pack4(float4 v, uint2& lo_out) {
    __nv_bfloat16 h0,l0,h1,l1,h2,l2,h3,l3;
    split2(v.x, h0, l0); split2(v.y, h1, l1);
    split2(v.z, h2, l2); split2(v.w, h3, l3);
    __nv_bfloat162 p01 = __halves2bfloat162(h0, h1);
    __nv_bfloat162 p23 = __halves2bfloat162(h2, h3);
    __nv_bfloat162 q01 = __halves2bfloat162(l0, l1);
    __nv_bfloat162 q23 = __halves2bfloat162(l2, l3);
    uint2 hi; hi.x = *(unsigned*)&p01; hi.y = *(unsigned*)&p23;
    lo_out.x = *(unsigned*)&q01; lo_out.y = *(unsigned*)&q23;
    return hi;
}

// D(16x8,f32) += A(16x16,bf16,row) * B(16x8,bf16,col)
__device__ __forceinline__ void mma16816(float* d, const unsigned* a, const unsigned* b) {
    asm volatile(
        "mma.sync.aligned.m16n8k16.row.col.f32.bf16.bf16.f32 "
        "{%0,%1,%2,%3}, {%4,%5,%6,%7}, {%8,%9}, {%0,%1,%2,%3};\n"
        : "+f"(d[0]), "+f"(d[1]), "+f"(d[2]), "+f"(d[3])
        : "r"(a[0]), "r"(a[1]), "r"(a[2]), "r"(a[3]), "r"(b[0]), "r"(b[1]));
}

__device__ __forceinline__ void ldmx4(unsigned* r, const void* p) {
    unsigned a = (unsigned)__cvta_generic_to_shared(p);
    asm volatile("ldmatrix.sync.aligned.m8n8.x4.shared.b16 {%0,%1,%2,%3}, [%4];"
        : "=r"(r[0]), "=r"(r[1]), "=r"(r[2]), "=r"(r[3]) : "r"(a));
}

// ---------------------------------------------------------------------------
// K1: fused QKV projection on tensor cores.  X read from DRAM ONCE.
// Out[m][d] = sum_e X[m][e]*W[d][e] for W in {wq,wk,wv} (exact bf16 weights).
// BM=64, BN=192 (64 per matrix), BK=32, 256 thr = 8 warps (2m x 4n).
// Warp tile 32m x 48n.  X split bf16 hi/lo -> 2 MMA products (exact weights).
// Register prefetch of next k-chunk hides streaming-X latency.
// Q written as bf16 hi/lo; K,V written fp32 for the energy path.
// ---------------------------------------------------------------------------
__global__ __launch_bounds__(256) void qkv_mma_kernel(
    const float* __restrict__ X,
    const float* __restrict__ Wq,
    const float* __restrict__ Wk,
    const float* __restrict__ Wv)
{
    __shared__ __nv_bfloat16 Xh[64][40];    // 80B row stride: ldmatrix conflict-free
    __shared__ __nv_bfloat16 Xl[64][40];
    __shared__ __nv_bfloat16 Wb[192][40];

    const int m0   = blockIdx.x * 64;
    const int tid  = threadIdx.x;
    const int warp = tid >> 5, lane = tid & 31;
    const int wm = warp >> 2, wn = warp & 3;
    const int lr = lane >> 2, lc = (lane & 3) * 2;

    float acc[2][6][4];
    #pragma unroll
    for (int i = 0; i < 2; i++)
        #pragma unroll
        for (int j = 0; j < 6; j++)
            #pragma unroll
            for (int q = 0; q < 4; q++) acc[i][j][q] = 0.f;

    // initial prefetch (k0 = 0)
    float4 xv[2], wv[6];
    #pragma unroll
    for (int t = 0; t < 2; t++) {
        int idx = t * 256 + tid;
        int r = idx >> 3, c = idx & 7;
        xv[t] = *(const float4*)&X[(size_t)(m0 + r) * E_ + c * 4];
    }
    #pragma unroll
    for (int t = 0; t < 6; t++) {
        int idx = t * 256 + tid;
        int r = idx >> 3, c = idx & 7;
        int sel = r >> 6, rr = r & 63;
        const float* W = (sel == 0) ? Wq : (sel == 1 ? Wk : Wv);
        wv[t] = *(const float4*)&W[(size_t)rr * E_ + c * 4];
    }

    for (int k0 = 0; k0 < E_; k0 += 32) {
        // store current chunk to smem (X split into hi/lo; W exact bf16)
        #pragma unroll
        for (int t = 0; t < 2; t++) {
            int idx = t * 256 + tid;
            int r = idx >> 3, c = idx & 7;
            uint2 lo;
            uint2 hi = split_pack4(xv[t], lo);
            *(uint2*)&Xh[r][c * 4] = hi;
            *(uint2*)&Xl[r][c * 4] = lo;
        }
        #pragma unroll
        for (int t = 0; t < 6; t++) {
            int idx = t * 256 + tid;
            int r = idx >> 3, c = idx & 7;
            __nv_bfloat162 p01 = __halves2bfloat162(__float2bfloat16_rn(wv[t].x),
                                                    __float2bfloat16_rn(wv[t].y));
            __nv_bfloat162 p23 = __halves2bfloat162(__float2bfloat16_rn(wv[t].z),
                                                    __float2bfloat16_rn(wv[t].w));
            uint2 u; u.x = *(unsigned*)&p01; u.y = *(unsigned*)&p23;
            *(uint2*)&Wb[r][c * 4] = u;
        }
        __syncthreads();

        // prefetch next chunk (in flight during compute)
        if (k0 + 32 < E_) {
            int kn = k0 + 32;
            #pragma unroll
            for (int t = 0; t < 2; t++) {
                int idx = t * 256 + tid;
                int r = idx >> 3, c = idx & 7;
                xv[t] = *(const float4*)&X[(size_t)(m0 + r) * E_ + kn + c * 4];
            }
            #pragma unroll
            for (int t = 0; t < 6; t++) {
                int idx = t * 256 + tid;
                int r = idx >> 3, c = idx & 7;
                int sel = r >> 6, rr = r & 63;
                const float* W = (sel == 0) ? Wq : (sel == 1 ? Wk : Wv);
                wv[t] = *(const float4*)&W[(size_t)rr * E_ + kn + c * 4];
            }
        }

        #pragma unroll
        for (int ks = 0; ks < 32; ks += 16) {
            unsigned bf[6][2];
            #pragma unroll
            for (int np = 0; np < 3; np++) {
                int n0 = wn * 48 + np * 16;
                const __nv_bfloat16* p =
                    &Wb[n0 + ((lane >> 4) << 3) + (lane & 7)][ks + (((lane >> 3) & 1) << 3)];
                unsigned t4[4];
                ldmx4(t4, p);
                bf[np*2][0] = t4[0]; bf[np*2][1] = t4[1];
                bf[np*2+1][0] = t4[2]; bf[np*2+1][1] = t4[3];
            }
            #pragma unroll
            for (int mt = 0; mt < 2; mt++) {
                int r0 = wm * 32 + mt * 16;
                unsigned ah[4], al[4];
                ldmx4(ah, &Xh[r0 + (lane & 15)][ks + ((lane >> 4) << 3)]);
                ldmx4(al, &Xl[r0 + (lane & 15)][ks + ((lane >> 4) << 3)]);
                #pragma unroll
                for (int nt = 0; nt < 6; nt++) mma16816(acc[mt][nt], ah, bf[nt]);
                #pragma unroll
                for (int nt = 0; nt < 6; nt++) mma16816(acc[mt][nt], al, bf[nt]);
            }
        }
        __syncthreads();
    }

    // Epilogue: fragment n-range selects Q / K / V (8 | 64, never crosses)
    #pragma unroll
    for (int mt = 0; mt < 2; mt++)
        #pragma unroll
        for (int nt = 0; nt < 6; nt++) {
            int ng  = wn * 48 + nt * 8;
            int sel = ng >> 6;
            int col = (ng & 63) + lc;
            int row = m0 + wm * 32 + mt * 16 + lr;
            if (sel == 0) {
                __nv_bfloat16 h0,l0,h1,l1;
                split2(acc[mt][nt][0], h0, l0); split2(acc[mt][nt][1], h1, l1);
                *(__nv_bfloat162*)&g_Qhi[(size_t)row * D_ + col] = __halves2bfloat162(h0, h1);
                *(__nv_bfloat162*)&g_Qlo[(size_t)row * D_ + col] = __halves2bfloat162(l0, l1);
                split2(acc[mt][nt][2], h0, l0); split2(acc[mt][nt][3], h1, l1);
                *(__nv_bfloat162*)&g_Qhi[(size_t)(row + 8) * D_ + col] = __halves2bfloat162(h0, h1);
                *(__nv_bfloat162*)&g_Qlo[(size_t)(row + 8) * D_ + col] = __halves2bfloat162(l0, l1);
            } else {
                float* Out = (sel == 1) ? g_K : g_V;
                *(float2*)&Out[(size_t)row * D_ + col] =
                    make_float2(acc[mt][nt][0], acc[mt][nt][1]);
                *(float2*)&Out[(size_t)(row + 8) * D_ + col] =
                    make_float2(acc[mt][nt][2], acc[mt][nt][3]);
            }
        }
}

// ---------------------------------------------------------------------------
// K2: energy partials (fp32 SIMT).  SPLITS=128 for wave balance.
// ---------------------------------------------------------------------------
__global__ __launch_bounds__(256) void energy_kernel()
{
    const int s = blockIdx.x;
    const int b = blockIdx.y;
    const float* Kb = g_K + (size_t)b * N_ * D_;
    const float* Vb = g_V + (size_t)b * N_ * D_;
    const int n_base = s * ROWS_PER_SPLIT;

    __shared__ float Ks[16][D_];
    __shared__ float Vs[16][D_];

    const int tid = threadIdx.x;
    const int ty  = tid >> 4;
    const int tx  = tid & 15;

    float acc[4][4];
    #pragma unroll
    for (int i = 0; i < 4; i++)
        #pragma unroll
        for (int j = 0; j < 4; j++) acc[i][j] = 0.f;

    for (int c = 0; c < ROWS_PER_SPLIT; c += 16) {
        int r  = tid >> 4;
        int c4 = tid & 15;
        *(float4*)&Ks[r][c4 * 4] = *(const float4*)&Kb[(size_t)(n_base + c + r) * D_ + c4 * 4];
        *(float4*)&Vs[r][c4 * 4] = *(const float4*)&Vb[(size_t)(n_base + c + r) * D_ + c4 * 4];
        __syncthreads();
        #pragma unroll
        for (int n = 0; n < 16; n++) {
            float kv[4], vv[4];
            *(float4*)&kv[0] = *(const float4*)&Ks[n][ty * 4];
            *(float4*)&vv[0] = *(const float4*)&Vs[n][tx * 4];
            #pragma unroll
            for (int i = 0; i < 4; i++)
                #pragma unroll
                for (int j = 0; j < 4; j++)
                    acc[i][j] += kv[i] * vv[j];
        }
        __syncthreads();
    }

    float* ep = g_epart + ((size_t)(b * SPLITS + s)) * (D_ * D_);
    #pragma unroll
    for (int i = 0; i < 4; i++)
        *(float4*)&ep[(ty * 4 + i) * D_ + tx * 4] =
            make_float4(acc[i][0], acc[i][1], acc[i][2], acc[i][3]);
}

// ---------------------------------------------------------------------------
// K3: reduce partials + fold wo; emit W2^T (=[e][d]) as bf16 hi/lo.
// ---------------------------------------------------------------------------
__global__ __launch_bounds__(256) void w2_kernel(const float* __restrict__ Wo)
{
    const int d = blockIdx.x;
    const int b = blockIdx.y;
    __shared__ float part[4][D_];
    __shared__ float row[D_];

    const int tid = threadIdx.x;
    const int d2  = tid & 63;
    const int sg  = tid >> 6;

    float sum = 0.f;
    for (int s = sg; s < SPLITS; s += 4)
        sum += g_epart[((size_t)(b * SPLITS + s)) * (D_ * D_) + d * D_ + d2];
    part[sg][d2] = sum;
    __syncthreads();
    if (tid < D_)
        row[tid] = (part[0][tid] + part[1][tid] + part[2][tid] + part[3][tid]) * SCALE_;
    __syncthreads();

    for (int e = tid; e < E_; e += 256) {
        const float4* wo4 = (const float4*)&Wo[(size_t)e * D_];
        float acc = 0.f;
        #pragma unroll
        for (int k4 = 0; k4 < D_ / 4; k4++) {
            float4 w = wo4[k4];
            acc += row[k4*4+0] * w.x + row[k4*4+1] * w.y
                 + row[k4*4+2] * w.z + row[k4*4+3] * w.w;
        }
        __nv_bfloat16 h, l;
        split2(acc, h, l);
        size_t idx = ((size_t)b * E_ + e) * D_ + d;
        g_W2thi[idx] = h;
        g_W2tlo[idx] = l;
    }
}

// ---------------------------------------------------------------------------
// K4: out[b][m][e] = sum_d Q[b][m][d] * W2[b][d][e] on tensor cores.
// 3-product split: Qh*Wh + Qh*Wl + Ql*Wh.  BM=128, BN=64, BK=32.
// 8 warps (4m x 2n), ldmatrix fragment loads, register prefetch of chunk 2.
// ---------------------------------------------------------------------------
__global__ __launch_bounds__(256) void out_mma_kernel(float* __restrict__ Out)
{
    __shared__ __nv_bfloat16 Qh[128][40];
    __shared__ __nv_bfloat16 Ql[128][40];
    __shared__ __nv_bfloat16 Wh[64][40];
    __shared__ __nv_bfloat16 Wl[64][40];

    const int m0 = blockIdx.x * 128;
    const int e0 = blockIdx.y * 64;
    const int b  = blockIdx.z;
    const int tid  = threadIdx.x;
    const int warp = tid >> 5, lane = tid & 31;
    const int wm = warp >> 1, wn = warp & 1;
    const int lr = lane >> 2, lc = (lane & 3) * 2;

    const size_t qbase = ((size_t)b * N_ + m0) * D_;
    const size_t wbase = ((size_t)b * E_ + e0) * D_;

    float acc[2][4][4];
    #pragma unroll
    for (int i = 0; i < 2; i++)
        #pragma unroll
        for (int j = 0; j < 4; j++)
            #pragma unroll
            for (int q = 0; q < 4; q++) acc[i][j][q] = 0.f;

    uint2 qhv[4], qlv[4], whv[2], wlv[2];
    #pragma unroll
    for (int t = 0; t < 4; t++) {
        int idx = t * 256 + tid;
        int r = idx >> 3, c = idx & 7;
        qhv[t] = *(const uint2*)&g_Qhi[qbase + (size_t)r * D_ + c * 4];
        qlv[t] = *(const uint2*)&g_Qlo[qbase + (size_t)r * D_ + c * 4];
    }
    #pragma unroll
    for (int t = 0; t < 2; t++) {
        int idx = t * 256 + tid;
        int r = idx >> 3, c = idx & 7;
        whv[t] = *(const uint2*)&g_W2thi[wbase + (size_t)r * D_ + c * 4];
        wlv[t] = *(const uint2*)&g_W2tlo[wbase + (size_t)r * D_ + c * 4];
    }

    for (int k0 = 0; k0 < D_; k0 += 32) {
        #pragma unroll
        for (int t = 0; t < 4; t++) {
            int idx = t * 256 + tid;
            int r = idx >> 3, c = idx & 7;
            *(uint2*)&Qh[r][c * 4] = qhv[t];
            *(uint2*)&Ql[r][c * 4] = qlv[t];
        }
        #pragma unroll
        for (int t = 0; t < 2; t++) {
            int idx = t * 256 + tid;
            int r = idx >> 3, c = idx & 7;
            *(uint2*)&Wh[r][c * 4] = whv[t];
            *(uint2*)&Wl[r][c * 4] = wlv[t];
        }
        __syncthreads();

        if (k0 + 32 < D_) {
            int kn = k0 + 32;
            #pragma unroll
            for (int t = 0; t < 4; t++) {
                int idx = t * 256 + tid;
                int r = idx >> 3, c = idx & 7;
                qhv[t] = *(const uint2*)&g_Qhi[qbase + (size_t)r * D_ + kn + c * 4];
                qlv[t] = *(const uint2*)&g_Qlo[qbase + (size_t)r * D_ + kn + c * 4];
            }
            #pragma unroll
            for (int t = 0; t < 2; t++) {
                int idx = t * 256 + tid;
                int r = idx >> 3, c = idx & 7;
                whv[t] = *(const uint2*)&g_W2thi[wbase + (size_t)r * D_ + kn + c * 4];
                wlv[t] = *(const uint2*)&g_W2tlo[wbase + (size_t)r * D_ + kn + c * 4];
            }
        }

        #pragma unroll
        for (int ks = 0; ks < 32; ks += 16) {
            unsigned bh[4][2], bl[4][2];
            #pragma unroll
            for (int np = 0; np < 2; np++) {
                int n0 = wn * 32 + np * 16;
                int nrow = n0 + ((lane >> 4) << 3) + (lane & 7);
                int ncol = ks + (((lane >> 3) & 1) << 3);
                unsigned t4[4];
                ldmx4(t4, &Wh[nrow][ncol]);
                bh[np*2][0] = t4[0]; bh[np*2][1] = t4[1];
                bh[np*2+1][0] = t4[2]; bh[np*2+1][1] = t4[3];
                ldmx4(t4, &Wl[nrow][ncol]);
                bl[np*2][0] = t4[0]; bl[np*2][1] = t4[1];
                bl[np*2+1][0] = t4[2]; bl[np*2+1][1] = t4[3];
            }
            #pragma unroll
            for (int mt = 0; mt < 2; mt++) {
                int r0 = wm * 32 + mt * 16;
                unsigned ah[4], al[4];
                ldmx4(ah, &Qh[r0 + (lane & 15)][ks + ((lane >> 4) << 3)]);
                ldmx4(al, &Ql[r0 + (lane & 15)][ks + ((lane >> 4) << 3)]);
                #pragma unroll
                for (int nt = 0; nt < 4; nt++) mma16816(acc[mt][nt], ah, bh[nt]);
                #pragma unroll
                for (int nt = 0; nt < 4; nt++) mma16816(acc[mt][nt], ah, bl[nt]);
                #pragma unroll
                for (int nt = 0; nt < 4; nt++) mma16816(acc[mt][nt], al, bh[nt]);
            }
        }
        __syncthreads();
    }

    #pragma unroll
    for (int mt = 0; mt < 2; mt++)
        #pragma unroll
        for (int nt = 0; nt < 4; nt++) {
            int row = m0 + wm * 32 + mt * 16 + lr;
            int col = e0 + wn * 32 + nt * 8 + lc;
            *(float2*)&Out[((size_t)b * N_ + row) * E_ + col] =
                make_float2(acc[mt][nt][0], acc[mt][nt][1]);
            *(float2*)&Out[((size_t)b * N_ + row + 8) * E_ + col] =
                make_float2(acc[mt][nt][2], acc[mt][nt][3]);
        }
}

// ---------------------------------------------------------------------------
extern "C" void kernel_launch(void* const* d_in, const int* in_sizes, int n_in,
                              void* d_out, int out_size)
{
    const float* x  = (const float*)d_in[0];
    const float* wq = (const float*)d_in[1];
    const float* wk = (const float*)d_in[2];
    const float* wv = (const float*)d_in[3];
    const float* wo = (const float*)d_in[4];
    float* out = (float*)d_out;

    qkv_mma_kernel<<<dim3(M_ / 64), 256>>>(x, wq, wk, wv);
    energy_kernel <<<dim3(SPLITS, B_), 256>>>();
    w2_kernel     <<<dim3(D_, B_), 256>>>(wo);
    out_mma_kernel<<<dim3(N_ / 128, E_ / 64, B_), 256>>>(out);
}

// round 6
// speedup vs baseline: 2.2991x; 1.0074x over previous
#include <cuda_runtime.h>
#include <cuda_bf16.h>

#define B_ 4
#define N_ 8192
#define E_ 1024
#define D_ 64
#define M_ (B_*N_)          // 32768 rows of X
#define SPLITS 128
#define ROWS_PER_SPLIT (N_/SPLITS)   // 64
#define SCALE_ 0.21650635094610965f  // sqrt(3/64)

// Scratch (device globals; no allocation allowed)
__device__ float g_K[M_*D_];
__device__ float g_V[M_*D_];
__device__ float g_epart[B_*SPLITS*D_*D_];
__device__ __nv_bfloat16 g_Qhi[M_*D_];
__device__ __nv_bfloat16 g_Qlo[M_*D_];
__device__ __nv_bfloat16 g_W2thi[B_*E_*D_];   // [b][e][d] transposed for B-frag
__device__ __nv_bfloat16 g_W2tlo[B_*E_*D_];

// ---------------------------------------------------------------------------
// helpers
// ---------------------------------------------------------------------------
__device__ __forceinline__ void split2(float x, __nv_bfloat16& h, __nv_bfloat16& l) {
    h = __float2bfloat16_rn(x);
    l = __float2bfloat16_rn(x - __bfloat162float(h));
}

__device__ __forceinline__ uint2 split_pack4(float4 v, uint2& lo_out) {
    __nv_bfloat16 h0,l0,h1,l1,h2,l2,h3,l3;
    split2(v.x, h0, l0); split2(v.y, h1, l1);
    split2(v.z, h2, l2); split2(v.w, h3, l3);
    __nv_bfloat162 p01 = __halves2bfloat162(h0, h1);
    __nv_bfloat162 p23 = __halves2bfloat162(h2, h3);
    __nv_bfloat162 q01 = __halves2bfloat162(l0, l1);
    __nv_bfloat162 q23 = __halves2bfloat162(l2, l3);
    uint2 hi; hi.x = *(unsigned*)&p01; hi.y = *(unsigned*)&p23;
    lo_out.x = *(unsigned*)&q01; lo_out.y = *(unsigned*)&q23;
    return hi;
}

// D(16x8,f32) += A(16x16,bf16,row) * B(16x8,bf16,col)
__device__ __forceinline__ void mma16816(float* d, const unsigned* a, const unsigned* b) {
    asm volatile(
        "mma.sync.aligned.m16n8k16.row.col.f32.bf16.bf16.f32 "
        "{%0,%1,%2,%3}, {%4,%5,%6,%7}, {%8,%9}, {%0,%1,%2,%3};\n"
        : "+f"(d[0]), "+f"(d[1]), "+f"(d[2]), "+f"(d[3])
        : "r"(a[0]), "r"(a[1]), "r"(a[2]), "r"(a[3]), "r"(b[0]), "r"(b[1]));
}

__device__ __forceinline__ void ldmx4(unsigned* r, const void* p) {
    unsigned a = (unsigned)__cvta_generic_to_shared(p);
    asm volatile("ldmatrix.sync.aligned.m8n8.x4.shared.b16 {%0,%1,%2,%3}, [%4];"
        : "=r"(r[0]), "=r"(r[1]), "=r"(r[2]), "=r"(r[3]) : "r"(a));
}

// ---------------------------------------------------------------------------
// K1: fused QKV projection on tensor cores.  X read from DRAM ONCE.
// Out[m][d] = sum_e X[m][e]*W[d][e] for W in {wq,wk,wv} (exact bf16 weights).
// BM=64, BN=192 (64 per matrix), BK=32, 256 thr = 8 warps (2m x 4n).
// Warp tile 32m x 48n.  X split bf16 hi/lo -> 2 MMA products (exact weights).
// Register prefetch of next k-chunk hides streaming-X latency.
// Q written as bf16 hi/lo; K,V written fp32 for the energy path.
// ---------------------------------------------------------------------------
__global__ __launch_bounds__(256) void qkv_mma_kernel(
    const float* __restrict__ X,
    const float* __restrict__ Wq,
    const float* __restrict__ Wk,
    const float* __restrict__ Wv)
{
    __shared__ __nv_bfloat16 Xh[64][40];    // 80B row stride: ldmatrix conflict-free
    __shared__ __nv_bfloat16 Xl[64][40];
    __shared__ __nv_bfloat16 Wb[192][40];

    const int m0   = blockIdx.x * 64;
    const int tid  = threadIdx.x;
    const int warp = tid >> 5, lane = tid & 31;
    const int wm = warp >> 2, wn = warp & 3;
    const int lr = lane >> 2, lc = (lane & 3) * 2;

    float acc[2][6][4];
    #pragma unroll
    for (int i = 0; i < 2; i++)
        #pragma unroll
        for (int j = 0; j < 6; j++)
            #pragma unroll
            for (int q = 0; q < 4; q++) acc[i][j][q] = 0.f;

    // initial prefetch (k0 = 0)
    float4 xv[2], wv[6];
    #pragma unroll
    for (int t = 0; t < 2; t++) {
        int idx = t * 256 + tid;
        int r = idx >> 3, c = idx & 7;
        xv[t] = *(const float4*)&X[(size_t)(m0 + r) * E_ + c * 4];
    }
    #pragma unroll
    for (int t = 0; t < 6; t++) {
        int idx = t * 256 + tid;
        int r = idx >> 3, c = idx & 7;
        int sel = r >> 6, rr = r & 63;
        const float* W = (sel == 0) ? Wq : (sel == 1 ? Wk : Wv);
        wv[t] = *(const float4*)&W[(size_t)rr * E_ + c * 4];
    }

    for (int k0 = 0; k0 < E_; k0 += 32) {
        // store current chunk to smem (X split into hi/lo; W exact bf16)
        #pragma unroll
        for (int t = 0; t < 2; t++) {
            int idx = t * 256 + tid;
            int r = idx >> 3, c = idx & 7;
            uint2 lo;
            uint2 hi = split_pack4(xv[t], lo);
            *(uint2*)&Xh[r][c * 4] = hi;
            *(uint2*)&Xl[r][c * 4] = lo;
        }
        #pragma unroll
        for (int t = 0; t < 6; t++) {
            int idx = t * 256 + tid;
            int r = idx >> 3, c = idx & 7;
            __nv_bfloat162 p01 = __halves2bfloat162(__float2bfloat16_rn(wv[t].x),
                                                    __float2bfloat16_rn(wv[t].y));
            __nv_bfloat162 p23 = __halves2bfloat162(__float2bfloat16_rn(wv[t].z),
                                                    __float2bfloat16_rn(wv[t].w));
            uint2 u; u.x = *(unsigned*)&p01; u.y = *(unsigned*)&p23;
            *(uint2*)&Wb[r][c * 4] = u;
        }
        __syncthreads();

        // prefetch next chunk (in flight during compute)
        if (k0 + 32 < E_) {
            int kn = k0 + 32;
            #pragma unroll
            for (int t = 0; t < 2; t++) {
                int idx = t * 256 + tid;
                int r = idx >> 3, c = idx & 7;
                xv[t] = *(const float4*)&X[(size_t)(m0 + r) * E_ + kn + c * 4];
            }
            #pragma unroll
            for (int t = 0; t < 6; t++) {
                int idx = t * 256 + tid;
                int r = idx >> 3, c = idx & 7;
                int sel = r >> 6, rr = r & 63;
                const float* W = (sel == 0) ? Wq : (sel == 1 ? Wk : Wv);
                wv[t] = *(const float4*)&W[(size_t)rr * E_ + kn + c * 4];
            }
        }

        #pragma unroll
        for (int ks = 0; ks < 32; ks += 16) {
            unsigned bf[6][2];
            #pragma unroll
            for (int np = 0; np < 3; np++) {
                int n0 = wn * 48 + np * 16;
                const __nv_bfloat16* p =
                    &Wb[n0 + ((lane >> 4) << 3) + (lane & 7)][ks + (((lane >> 3) & 1) << 3)];
                unsigned t4[4];
                ldmx4(t4, p);
                bf[np*2][0] = t4[0]; bf[np*2][1] = t4[1];
                bf[np*2+1][0] = t4[2]; bf[np*2+1][1] = t4[3];
            }
            #pragma unroll
            for (int mt = 0; mt < 2; mt++) {
                int r0 = wm * 32 + mt * 16;
                unsigned ah[4], al[4];
                ldmx4(ah, &Xh[r0 + (lane & 15)][ks + ((lane >> 4) << 3)]);
                ldmx4(al, &Xl[r0 + (lane & 15)][ks + ((lane >> 4) << 3)]);
                #pragma unroll
                for (int nt = 0; nt < 6; nt++) mma16816(acc[mt][nt], ah, bf[nt]);
                #pragma unroll
                for (int nt = 0; nt < 6; nt++) mma16816(acc[mt][nt], al, bf[nt]);
            }
        }
        __syncthreads();
    }

    // Epilogue: fragment n-range selects Q / K / V (8 | 64, never crosses)
    #pragma unroll
    for (int mt = 0; mt < 2; mt++)
        #pragma unroll
        for (int nt = 0; nt < 6; nt++) {
            int ng  = wn * 48 + nt * 8;
            int sel = ng >> 6;
            int col = (ng & 63) + lc;
            int row = m0 + wm * 32 + mt * 16 + lr;
            if (sel == 0) {
                __nv_bfloat16 h0,l0,h1,l1;
                split2(acc[mt][nt][0], h0, l0); split2(acc[mt][nt][1], h1, l1);
                *(__nv_bfloat162*)&g_Qhi[(size_t)row * D_ + col] = __halves2bfloat162(h0, h1);
                *(__nv_bfloat162*)&g_Qlo[(size_t)row * D_ + col] = __halves2bfloat162(l0, l1);
                split2(acc[mt][nt][2], h0, l0); split2(acc[mt][nt][3], h1, l1);
                *(__nv_bfloat162*)&g_Qhi[(size_t)(row + 8) * D_ + col] = __halves2bfloat162(h0, h1);
                *(__nv_bfloat162*)&g_Qlo[(size_t)(row + 8) * D_ + col] = __halves2bfloat162(l0, l1);
            } else {
                float* Out = (sel == 1) ? g_K : g_V;
                *(float2*)&Out[(size_t)row * D_ + col] =
                    make_float2(acc[mt][nt][0], acc[mt][nt][1]);
                *(float2*)&Out[(size_t)(row + 8) * D_ + col] =
                    make_float2(acc[mt][nt][2], acc[mt][nt][3]);
            }
        }
}

// ---------------------------------------------------------------------------
// K2: energy partials (fp32 SIMT).  SPLITS=128 for wave balance.
// ---------------------------------------------------------------------------
__global__ __launch_bounds__(256) void energy_kernel()
{
    const int s = blockIdx.x;
    const int b = blockIdx.y;
    const float* Kb = g_K + (size_t)b * N_ * D_;
    const float* Vb = g_V + (size_t)b * N_ * D_;
    const int n_base = s * ROWS_PER_SPLIT;

    __shared__ float Ks[16][D_];
    __shared__ float Vs[16][D_];

    const int tid = threadIdx.x;
    const int ty  = tid >> 4;
    const int tx  = tid & 15;

    float acc[4][4];
    #pragma unroll
    for (int i = 0; i < 4; i++)
        #pragma unroll
        for (int j = 0; j < 4; j++) acc[i][j] = 0.f;

    for (int c = 0; c < ROWS_PER_SPLIT; c += 16) {
        int r  = tid >> 4;
        int c4 = tid & 15;
        *(float4*)&Ks[r][c4 * 4] = *(const float4*)&Kb[(size_t)(n_base + c + r) * D_ + c4 * 4];
        *(float4*)&Vs[r][c4 * 4] = *(const float4*)&Vb[(size_t)(n_base + c + r) * D_ + c4 * 4];
        __syncthreads();
        #pragma unroll
        for (int n = 0; n < 16; n++) {
            float kv[4], vv[4];
            *(float4*)&kv[0] = *(const float4*)&Ks[n][ty * 4];
            *(float4*)&vv[0] = *(const float4*)&Vs[n][tx * 4];
            #pragma unroll
            for (int i = 0; i < 4; i++)
                #pragma unroll
                for (int j = 0; j < 4; j++)
                    acc[i][j] += kv[i] * vv[j];
        }
        __syncthreads();
    }

    float* ep = g_epart + ((size_t)(b * SPLITS + s)) * (D_ * D_);
    #pragma unroll
    for (int i = 0; i < 4; i++)
        *(float4*)&ep[(ty * 4 + i) * D_ + tx * 4] =
            make_float4(acc[i][0], acc[i][1], acc[i][2], acc[i][3]);
}

// ---------------------------------------------------------------------------
// K3: reduce partials + fold wo; emit W2^T (=[e][d]) as bf16 hi/lo.
// ---------------------------------------------------------------------------
__global__ __launch_bounds__(256) void w2_kernel(const float* __restrict__ Wo)
{
    const int d = blockIdx.x;
    const int b = blockIdx.y;
    __shared__ float part[4][D_];
    __shared__ float row[D_];

    const int tid = threadIdx.x;
    const int d2  = tid & 63;
    const int sg  = tid >> 6;

    float sum = 0.f;
    for (int s = sg; s < SPLITS; s += 4)
        sum += g_epart[((size_t)(b * SPLITS + s)) * (D_ * D_) + d * D_ + d2];
    part[sg][d2] = sum;
    __syncthreads();
    if (tid < D_)
        row[tid] = (part[0][tid] + part[1][tid] + part[2][tid] + part[3][tid]) * SCALE_;
    __syncthreads();

    for (int e = tid; e < E_; e += 256) {
        const float4* wo4 = (const float4*)&Wo[(size_t)e * D_];
        float acc = 0.f;
        #pragma unroll
        for (int k4 = 0; k4 < D_ / 4; k4++) {
            float4 w = wo4[k4];
            acc += row[k4*4+0] * w.x + row[k4*4+1] * w.y
                 + row[k4*4+2] * w.z + row[k4*4+3] * w.w;
        }
        __nv_bfloat16 h, l;
        split2(acc, h, l);
        size_t idx = ((size_t)b * E_ + e) * D_ + d;
        g_W2thi[idx] = h;
        g_W2tlo[idx] = l;
    }
}

// ---------------------------------------------------------------------------
// K4: out[b][m][e] = sum_d Q[b][m][d] * W2[b][d][e] on tensor cores.
// 3-product split: Qh*Wh + Qh*Wl + Ql*Wh.  BM=128, BN=64, BK=32.
// 8 warps (4m x 2n), ldmatrix fragment loads, register prefetch of chunk 2.
// ---------------------------------------------------------------------------
__global__ __launch_bounds__(256) void out_mma_kernel(float* __restrict__ Out)
{
    __shared__ __nv_bfloat16 Qh[128][40];
    __shared__ __nv_bfloat16 Ql[128][40];
    __shared__ __nv_bfloat16 Wh[64][40];
    __shared__ __nv_bfloat16 Wl[64][40];

    const int m0 = blockIdx.x * 128;
    const int e0 = blockIdx.y * 64;
    const int b  = blockIdx.z;
    const int tid  = threadIdx.x;
    const int warp = tid >> 5, lane = tid & 31;
    const int wm = warp >> 1, wn = warp & 1;
    const int lr = lane >> 2, lc = (lane & 3) * 2;

    const size_t qbase = ((size_t)b * N_ + m0) * D_;
    const size_t wbase = ((size_t)b * E_ + e0) * D_;

    float acc[2][4][4];
    #pragma unroll
    for (int i = 0; i < 2; i++)
        #pragma unroll
        for (int j = 0; j < 4; j++)
            #pragma unroll
            for (int q = 0; q < 4; q++) acc[i][j][q] = 0.f;

    uint2 qhv[4], qlv[4], whv[2], wlv[2];
    #pragma unroll
    for (int t = 0; t < 4; t++) {
        int idx = t * 256 + tid;
        int r = idx >> 3, c = idx & 7;
        qhv[t] = *(const uint2*)&g_Qhi[qbase + (size_t)r * D_ + c * 4];
        qlv[t] = *(const uint2*)&g_Qlo[qbase + (size_t)r * D_ + c * 4];
    }
    #pragma unroll
    for (int t = 0; t < 2; t++) {
        int idx = t * 256 + tid;
        int r = idx >> 3, c = idx & 7;
        whv[t] = *(const uint2*)&g_W2thi[wbase + (size_t)r * D_ + c * 4];
        wlv[t] = *(const uint2*)&g_W2tlo[wbase + (size_t)r * D_ + c * 4];
    }

    for (int k0 = 0; k0 < D_; k0 += 32) {
        #pragma unroll
        for (int t = 0; t < 4; t++) {
            int idx = t * 256 + tid;
            int r = idx >> 3, c = idx & 7;
            *(uint2*)&Qh[r][c * 4] = qhv[t];
            *(uint2*)&Ql[r][c * 4] = qlv[t];
        }
        #pragma unroll
        for (int t = 0; t < 2; t++) {
            int idx = t * 256 + tid;
            int r = idx >> 3, c = idx & 7;
            *(uint2*)&Wh[r][c * 4] = whv[t];
            *(uint2*)&Wl[r][c * 4] = wlv[t];
        }
        __syncthreads();

        if (k0 + 32 < D_) {
            int kn = k0 + 32;
            #pragma unroll
            for (int t = 0; t < 4; t++) {
                int idx = t * 256 + tid;
                int r = idx >> 3, c = idx & 7;
                qhv[t] = *(const uint2*)&g_Qhi[qbase + (size_t)r * D_ + kn + c * 4];
                qlv[t] = *(const uint2*)&g_Qlo[qbase + (size_t)r * D_ + kn + c * 4];
            }
            #pragma unroll
            for (int t = 0; t < 2; t++) {
                int idx = t * 256 + tid;
                int r = idx >> 3, c = idx & 7;
                whv[t] = *(const uint2*)&g_W2thi[wbase + (size_t)r * D_ + kn + c * 4];
                wlv[t] = *(const uint2*)&g_W2tlo[wbase + (size_t)r * D_ + kn + c * 4];
            }
        }

        #pragma unroll
        for (int ks = 0; ks < 32; ks += 16) {
            unsigned bh[4][2], bl[4][2];
            #pragma unroll
            for (int np = 0; np < 2; np++) {
                int n0 = wn * 32 + np * 16;
                int nrow = n0 + ((lane >> 4) << 3) + (lane & 7);
                int ncol = ks + (((lane >> 3) & 1) << 3);
                unsigned t4[4];
                ldmx4(t4, &Wh[nrow][ncol]);
                bh[np*2][0] = t4[0]; bh[np*2][1] = t4[1];
                bh[np*2+1][0] = t4[2]; bh[np*2+1][1] = t4[3];
                ldmx4(t4, &Wl[nrow][ncol]);
                bl[np*2][0] = t4[0]; bl[np*2][1] = t4[1];
                bl[np*2+1][0] = t4[2]; bl[np*2+1][1] = t4[3];
            }
            #pragma unroll
            for (int mt = 0; mt < 2; mt++) {
                int r0 = wm * 32 + mt * 16;
                unsigned ah[4], al[4];
                ldmx4(ah, &Qh[r0 + (lane & 15)][ks + ((lane >> 4) << 3)]);
                ldmx4(al, &Ql[r0 + (lane & 15)][ks + ((lane >> 4) << 3)]);
                #pragma unroll
                for (int nt = 0; nt < 4; nt++) mma16816(acc[mt][nt], ah, bh[nt]);
                #pragma unroll
                for (int nt = 0; nt < 4; nt++) mma16816(acc[mt][nt], ah, bl[nt]);
                #pragma unroll
                for (int nt = 0; nt < 4; nt++) mma16816(acc[mt][nt], al, bh[nt]);
            }
        }
        __syncthreads();
    }

    #pragma unroll
    for (int mt = 0; mt < 2; mt++)
        #pragma unroll
        for (int nt = 0; nt < 4; nt++) {
            int row = m0 + wm * 32 + mt * 16 + lr;
            int col = e0 + wn * 32 + nt * 8 + lc;
            *(float2*)&Out[((size_t)b * N_ + row) * E_ + col] =
                make_float2(acc[mt][nt][0], acc[mt][nt][1]);
            *(float2*)&Out[((size_t)b * N_ + row + 8) * E_ + col] =
                make_float2(acc[mt][nt][2], acc[mt][nt][3]);
        }
}

// ---------------------------------------------------------------------------
extern "C" void kernel_launch(void* const* d_in, const int* in_sizes, int n_in,
                              void* d_out, int out_size)
{
    const float* x  = (const float*)d_in[0];
    const float* wq = (const float*)d_in[1];
    const float* wk = (const float*)d_in[2];
    const float* wv = (const float*)d_in[3];
    const float* wo = (const float*)d_in[4];
    float* out = (float*)d_out;

    qkv_mma_kernel<<<dim3(M_ / 64), 256>>>(x, wq, wk, wv);
    energy_kernel <<<dim3(SPLITS, B_), 256>>>();
    w2_kernel     <<<dim3(D_, B_), 256>>>(wo);
    out_mma_kernel<<<dim3(N_ / 128, E_ / 64, B_), 256>>>(out);
}

// round 8
// speedup vs baseline: 2.6852x; 1.1679x over previous
#include <cuda_runtime.h>
#include <cuda_bf16.h>
#include <cstdint>

#define B_ 4
#define N_ 8192
#define E_ 1024
#define D_ 64
#define M_ (B_*N_)          // 32768 rows of X
#define SPLITS 128
#define ROWS_PER_SPLIT (N_/SPLITS)   // 64
#define SCALE_ 0.21650635094610965f  // sqrt(3/64)

// Scratch (device globals; no allocation allowed)
__device__ float g_K[M_*D_];
__device__ float g_V[M_*D_];
__device__ float g_epart[B_*SPLITS*D_*D_];
__device__ __nv_bfloat16 g_Qhi[M_*D_];
__device__ __nv_bfloat16 g_Qlo[M_*D_];
__device__ __nv_bfloat16 g_W2thi[B_*E_*D_];   // [b][e][d] transposed for B-frag
__device__ __nv_bfloat16 g_W2tlo[B_*E_*D_];
__device__ __nv_bfloat16 g_Wb[192*E_];        // [n][k]: rows 0-63 wq, 64-127 wk, 128-191 wv

// ---------------------------------------------------------------------------
// helpers
// ---------------------------------------------------------------------------
__device__ __forceinline__ void split2(float x, __nv_bfloat16& h, __nv_bfloat16& l) {
    h = __float2bfloat16_rn(x);
    l = __float2bfloat16_rn(x - __bfloat162float(h));
}

__device__ __forceinline__ uint2 split_pack4(float4 v, uint2& lo_out) {
    __nv_bfloat16 h0,l0,h1,l1,h2,l2,h3,l3;
    split2(v.x, h0, l0); split2(v.y, h1, l1);
    split2(v.z, h2, l2); split2(v.w, h3, l3);
    __nv_bfloat162 p01 = __halves2bfloat162(h0, h1);
    __nv_bfloat162 p23 = __halves2bfloat162(h2, h3);
    __nv_bfloat162 q01 = __halves2bfloat162(l0, l1);
    __nv_bfloat162 q23 = __halves2bfloat162(l2, l3);
    uint2 hi; hi.x = *(unsigned*)&p01; hi.y = *(unsigned*)&p23;
    lo_out.x = *(unsigned*)&q01; lo_out.y = *(unsigned*)&q23;
    return hi;
}

// D(16x8,f32) += A(16x16,bf16,row) * B(16x8,bf16,col)
__device__ __forceinline__ void mma16816(float* d, const unsigned* a, const unsigned* b) {
    asm volatile(
        "mma.sync.aligned.m16n8k16.row.col.f32.bf16.bf16.f32 "
        "{%0,%1,%2,%3}, {%4,%5,%6,%7}, {%8,%9}, {%0,%1,%2,%3};\n"
        : "+f"(d[0]), "+f"(d[1]), "+f"(d[2]), "+f"(d[3])
        : "r"(a[0]), "r"(a[1]), "r"(a[2]), "r"(a[3]), "r"(b[0]), "r"(b[1]));
}

__device__ __forceinline__ void ldmx4(unsigned* r, const void* p) {
    unsigned a = (unsigned)__cvta_generic_to_shared(p);
    asm volatile("ldmatrix.sync.aligned.m8n8.x4.shared.b16 {%0,%1,%2,%3}, [%4];"
        : "=r"(r[0]), "=r"(r[1]), "=r"(r[2]), "=r"(r[3]) : "r"(a));
}

// ---------------------------------------------------------------------------
// K0: pre-convert weights to bf16 (exact: values are +-2^-5), layout [n][k]:
// rows 0-63 wq, 64-127 wk, 128-191 wv.
// ---------------------------------------------------------------------------
__global__ __launch_bounds__(256) void wconv_kernel(
    const float* __restrict__ Wq, const float* __restrict__ Wk, const float* __restrict__ Wv)
{
    int i = blockIdx.x * 256 + threadIdx.x;   // one float4 (4 elems) each
    int n = i >> 8;                            // 1024/4 = 256 groups per row
    int g = i & 255;
    const float* W = (n < 64) ? Wq : (n < 128 ? Wk : Wv);
    int rr = n & 63;
    float4 v = *(const float4*)&W[(size_t)rr * E_ + g * 4];
    __nv_bfloat162 p01 = __halves2bfloat162(__float2bfloat16_rn(v.x), __float2bfloat16_rn(v.y));
    __nv_bfloat162 p23 = __halves2bfloat162(__float2bfloat16_rn(v.z), __float2bfloat16_rn(v.w));
    uint2 u; u.x = *(unsigned*)&p01; u.y = *(unsigned*)&p23;
    *(uint2*)&g_Wb[(size_t)n * E_ + g * 4] = u;
}

// ---------------------------------------------------------------------------
// K1: fused QKV projection, legacy MMA.  X read from DRAM once; W read as
// pre-converted bf16 (no in-loop cvt).  BM=64, BN=192, BK=32, 8 warps (2m x 4n),
// warp tile 32m x 48n.  X split bf16 hi/lo -> 2 MMA products (exact weights).
// ---------------------------------------------------------------------------
__global__ __launch_bounds__(256) void qkv_mma_kernel(const float* __restrict__ X)
{
    __shared__ __nv_bfloat16 Xh[64][40];    // 80B row stride: ldmatrix conflict-free
    __shared__ __nv_bfloat16 Xl[64][40];
    __shared__ __nv_bfloat16 Wb[192][40];

    const int m0   = blockIdx.x * 64;
    const int tid  = threadIdx.x;
    const int warp = tid >> 5, lane = tid & 31;
    const int wm = warp >> 2, wn = warp & 3;
    const int lr = lane >> 2, lc = (lane & 3) * 2;

    float acc[2][6][4];
    #pragma unroll
    for (int i = 0; i < 2; i++)
        #pragma unroll
        for (int j = 0; j < 6; j++)
            #pragma unroll
            for (int q = 0; q < 4; q++) acc[i][j][q] = 0.f;

    // initial prefetch (k0 = 0): X 64x32 fp32 = 512 float4 (2/thr);
    // W 192x32 bf16 = 768 uint4 (3/thr)
    float4 xv[2];
    uint4  wvb[3];
    #pragma unroll
    for (int t = 0; t < 2; t++) {
        int idx = t * 256 + tid;
        int r = idx >> 3, c = idx & 7;
        xv[t] = *(const float4*)&X[(size_t)(m0 + r) * E_ + c * 4];
    }
    #pragma unroll
    for (int t = 0; t < 3; t++) {
        int idx = t * 256 + tid;
        int r = idx >> 2, q = idx & 3;
        wvb[t] = *(const uint4*)&g_Wb[(size_t)r * E_ + q * 8];
    }

    for (int k0 = 0; k0 < E_; k0 += 32) {
        // store current chunk to smem (X split into hi/lo; W already bf16)
        #pragma unroll
        for (int t = 0; t < 2; t++) {
            int idx = t * 256 + tid;
            int r = idx >> 3, c = idx & 7;
            uint2 lo;
            uint2 hi = split_pack4(xv[t], lo);
            *(uint2*)&Xh[r][c * 4] = hi;
            *(uint2*)&Xl[r][c * 4] = lo;
        }
        #pragma unroll
        for (int t = 0; t < 3; t++) {
            int idx = t * 256 + tid;
            int r = idx >> 2, q = idx & 3;
            *(uint4*)&Wb[r][q * 8] = wvb[t];
        }
        __syncthreads();

        // prefetch next chunk (in flight during compute)
        if (k0 + 32 < E_) {
            int kn = k0 + 32;
            #pragma unroll
            for (int t = 0; t < 2; t++) {
                int idx = t * 256 + tid;
                int r = idx >> 3, c = idx & 7;
                xv[t] = *(const float4*)&X[(size_t)(m0 + r) * E_ + kn + c * 4];
            }
            #pragma unroll
            for (int t = 0; t < 3; t++) {
                int idx = t * 256 + tid;
                int r = idx >> 2, q = idx & 3;
                wvb[t] = *(const uint4*)&g_Wb[(size_t)r * E_ + kn + q * 8];
            }
        }

        #pragma unroll
        for (int ks = 0; ks < 32; ks += 16) {
            unsigned bf[6][2];
            #pragma unroll
            for (int np = 0; np < 3; np++) {
                int n0 = wn * 48 + np * 16;
                const __nv_bfloat16* p =
                    &Wb[n0 + ((lane >> 4) << 3) + (lane & 7)][ks + (((lane >> 3) & 1) << 3)];
                unsigned t4[4];
                ldmx4(t4, p);
                bf[np*2][0] = t4[0]; bf[np*2][1] = t4[1];
                bf[np*2+1][0] = t4[2]; bf[np*2+1][1] = t4[3];
            }
            #pragma unroll
            for (int mt = 0; mt < 2; mt++) {
                int r0 = wm * 32 + mt * 16;
                unsigned ah[4], al[4];
                ldmx4(ah, &Xh[r0 + (lane & 15)][ks + ((lane >> 4) << 3)]);
                ldmx4(al, &Xl[r0 + (lane & 15)][ks + ((lane >> 4) << 3)]);
                #pragma unroll
                for (int nt = 0; nt < 6; nt++) mma16816(acc[mt][nt], ah, bf[nt]);
                #pragma unroll
                for (int nt = 0; nt < 6; nt++) mma16816(acc[mt][nt], al, bf[nt]);
            }
        }
        __syncthreads();
    }

    // Epilogue: fragment n-range selects Q / K / V (8 | 64, never crosses)
    #pragma unroll
    for (int mt = 0; mt < 2; mt++)
        #pragma unroll
        for (int nt = 0; nt < 6; nt++) {
            int ng  = wn * 48 + nt * 8;
            int sel = ng >> 6;
            int col = (ng & 63) + lc;
            int row = m0 + wm * 32 + mt * 16 + lr;
            if (sel == 0) {
                __nv_bfloat16 h0,l0,h1,l1;
                split2(acc[mt][nt][0], h0, l0); split2(acc[mt][nt][1], h1, l1);
                *(__nv_bfloat162*)&g_Qhi[(size_t)row * D_ + col] = __halves2bfloat162(h0, h1);
                *(__nv_bfloat162*)&g_Qlo[(size_t)row * D_ + col] = __halves2bfloat162(l0, l1);
                split2(acc[mt][nt][2], h0, l0); split2(acc[mt][nt][3], h1, l1);
                *(__nv_bfloat162*)&g_Qhi[(size_t)(row + 8) * D_ + col] = __halves2bfloat162(h0, h1);
                *(__nv_bfloat162*)&g_Qlo[(size_t)(row + 8) * D_ + col] = __halves2bfloat162(l0, l1);
            } else {
                float* Out = (sel == 1) ? g_K : g_V;
                *(float2*)&Out[(size_t)row * D_ + col] =
                    make_float2(acc[mt][nt][0], acc[mt][nt][1]);
                *(float2*)&Out[(size_t)(row + 8) * D_ + col] =
                    make_float2(acc[mt][nt][2], acc[mt][nt][3]);
            }
        }
}

// ---------------------------------------------------------------------------
// K2: energy partials (fp32 SIMT).
// ---------------------------------------------------------------------------
__global__ __launch_bounds__(256) void energy_kernel()
{
    const int s = blockIdx.x;
    const int b = blockIdx.y;
    const float* Kb = g_K + (size_t)b * N_ * D_;
    const float* Vb = g_V + (size_t)b * N_ * D_;
    const int n_base = s * ROWS_PER_SPLIT;

    __shared__ float Ks[16][D_];
    __shared__ float Vs[16][D_];

    const int tid = threadIdx.x;
    const int ty  = tid >> 4;
    const int tx  = tid & 15;

    float acc[4][4];
    #pragma unroll
    for (int i = 0; i < 4; i++)
        #pragma unroll
        for (int j = 0; j < 4; j++) acc[i][j] = 0.f;

    for (int c = 0; c < ROWS_PER_SPLIT; c += 16) {
        int r  = tid >> 4;
        int c4 = tid & 15;
        *(float4*)&Ks[r][c4 * 4] = *(const float4*)&Kb[(size_t)(n_base + c + r) * D_ + c4 * 4];
        *(float4*)&Vs[r][c4 * 4] = *(const float4*)&Vb[(size_t)(n_base + c + r) * D_ + c4 * 4];
        __syncthreads();
        #pragma unroll
        for (int n = 0; n < 16; n++) {
            float kv[4], vv[4];
            *(float4*)&kv[0] = *(const float4*)&Ks[n][ty * 4];
            *(float4*)&vv[0] = *(const float4*)&Vs[n][tx * 4];
            #pragma unroll
            for (int i = 0; i < 4; i++)
                #pragma unroll
                for (int j = 0; j < 4; j++)
                    acc[i][j] += kv[i] * vv[j];
        }
        __syncthreads();
    }

    float* ep = g_epart + ((size_t)(b * SPLITS + s)) * (D_ * D_);
    #pragma unroll
    for (int i = 0; i < 4; i++)
        *(float4*)&ep[(ty * 4 + i) * D_ + tx * 4] =
            make_float4(acc[i][0], acc[i][1], acc[i][2], acc[i][3]);
}

// ---------------------------------------------------------------------------
// K3: reduce partials + fold wo; emit W2^T (=[e][d]) as bf16 hi/lo.
// ---------------------------------------------------------------------------
__global__ __launch_bounds__(256) void w2_kernel(const float* __restrict__ Wo)
{
    const int d = blockIdx.x;
    const int b = blockIdx.y;
    __shared__ float part[4][D_];
    __shared__ float row[D_];

    const int tid = threadIdx.x;
    const int d2  = tid & 63;
    const int sg  = tid >> 6;

    float sum = 0.f;
    for (int s = sg; s < SPLITS; s += 4)
        sum += g_epart[((size_t)(b * SPLITS + s)) * (D_ * D_) + d * D_ + d2];
    part[sg][d2] = sum;
    __syncthreads();
    if (tid < D_)
        row[tid] = (part[0][tid] + part[1][tid] + part[2][tid] + part[3][tid]) * SCALE_;
    __syncthreads();

    for (int e = tid; e < E_; e += 256) {
        const float4* wo4 = (const float4*)&Wo[(size_t)e * D_];
        float acc = 0.f;
        #pragma unroll
        for (int k4 = 0; k4 < D_ / 4; k4++) {
            float4 w = wo4[k4];
            acc += row[k4*4+0] * w.x + row[k4*4+1] * w.y
                 + row[k4*4+2] * w.z + row[k4*4+3] * w.w;
        }
        __nv_bfloat16 h, l;
        split2(acc, h, l);
        size_t idx = ((size_t)b * E_ + e) * D_ + d;
        g_W2thi[idx] = h;
        g_W2tlo[idx] = l;
    }
}

// ---------------------------------------------------------------------------
// K4: out[b][m][e] = sum_d Q[b][m][d] * W2[b][d][e] on tensor cores.
// 3-product split: Qh*Wh + Qh*Wl + Ql*Wh.  BM=128, BN=128, BK=32.
// 8 warps (4m x 2n), warp tile 32m x 64n: 12 ldmatrix / 48 HMMA per ks
// (ratio 4.0 vs round-6's 1.5) -> LDSM pressure cut 2.7x.
// ---------------------------------------------------------------------------
__global__ __launch_bounds__(256) void out_mma_kernel(float* __restrict__ Out)
{
    __shared__ __nv_bfloat16 Qh[128][40];
    __shared__ __nv_bfloat16 Ql[128][40];
    __shared__ __nv_bfloat16 Wh[128][40];
    __shared__ __nv_bfloat16 Wl[128][40];

    const int m0 = blockIdx.x * 128;
    const int e0 = blockIdx.y * 128;
    const int b  = blockIdx.z;
    const int tid  = threadIdx.x;
    const int warp = tid >> 5, lane = tid & 31;
    const int wm = warp >> 1, wn = warp & 1;
    const int lr = lane >> 2, lc = (lane & 3) * 2;

    const size_t qbase = ((size_t)b * N_ + m0) * D_;
    const size_t wbase = ((size_t)b * E_ + e0) * D_;

    float acc[2][8][4];
    #pragma unroll
    for (int i = 0; i < 2; i++)
        #pragma unroll
        for (int j = 0; j < 8; j++)
            #pragma unroll
            for (int q = 0; q < 4; q++) acc[i][j][q] = 0.f;

    // prefetch chunk 0: Q 128x32 bf16 = 1024 uint2 (4/thr); W same
    uint2 qhv[4], qlv[4], whv[4], wlv[4];
    #pragma unroll
    for (int t = 0; t < 4; t++) {
        int idx = t * 256 + tid;
        int r = idx >> 3, c = idx & 7;
        qhv[t] = *(const uint2*)&g_Qhi[qbase + (size_t)r * D_ + c * 4];
        qlv[t] = *(const uint2*)&g_Qlo[qbase + (size_t)r * D_ + c * 4];
        whv[t] = *(const uint2*)&g_W2thi[wbase + (size_t)r * D_ + c * 4];
        wlv[t] = *(const uint2*)&g_W2tlo[wbase + (size_t)r * D_ + c * 4];
    }

    for (int k0 = 0; k0 < D_; k0 += 32) {
        #pragma unroll
        for (int t = 0; t < 4; t++) {
            int idx = t * 256 + tid;
            int r = idx >> 3, c = idx & 7;
            *(uint2*)&Qh[r][c * 4] = qhv[t];
            *(uint2*)&Ql[r][c * 4] = qlv[t];
            *(uint2*)&Wh[r][c * 4] = whv[t];
            *(uint2*)&Wl[r][c * 4] = wlv[t];
        }
        __syncthreads();

        if (k0 + 32 < D_) {
            int kn = k0 + 32;
            #pragma unroll
            for (int t = 0; t < 4; t++) {
                int idx = t * 256 + tid;
                int r = idx >> 3, c = idx & 7;
                qhv[t] = *(const uint2*)&g_Qhi[qbase + (size_t)r * D_ + kn + c * 4];
                qlv[t] = *(const uint2*)&g_Qlo[qbase + (size_t)r * D_ + kn + c * 4];
                whv[t] = *(const uint2*)&g_W2thi[wbase + (size_t)r * D_ + kn + c * 4];
                wlv[t] = *(const uint2*)&g_W2tlo[wbase + (size_t)r * D_ + kn + c * 4];
            }
        }

        #pragma unroll
        for (int ks = 0; ks < 32; ks += 16) {
            unsigned bh[8][2], bl[8][2];
            #pragma unroll
            for (int np = 0; np < 4; np++) {
                int nrow = wn * 64 + np * 16 + ((lane >> 4) << 3) + (lane & 7);
                int ncol = ks + (((lane >> 3) & 1) << 3);
                unsigned t4[4];
                ldmx4(t4, &Wh[nrow][ncol]);
                bh[np*2][0] = t4[0]; bh[np*2][1] = t4[1];
                bh[np*2+1][0] = t4[2]; bh[np*2+1][1] = t4[3];
                ldmx4(t4, &Wl[nrow][ncol]);
                bl[np*2][0] = t4[0]; bl[np*2][1] = t4[1];
                bl[np*2+1][0] = t4[2]; bl[np*2+1][1] = t4[3];
            }
            #pragma unroll
            for (int mt = 0; mt < 2; mt++) {
                int r0 = wm * 32 + mt * 16;
                unsigned ah[4], al[4];
                ldmx4(ah, &Qh[r0 + (lane & 15)][ks + ((lane >> 4) << 3)]);
                ldmx4(al, &Ql[r0 + (lane & 15)][ks + ((lane >> 4) << 3)]);
                #pragma unroll
                for (int nt = 0; nt < 8; nt++) mma16816(acc[mt][nt], ah, bh[nt]);
                #pragma unroll
                for (int nt = 0; nt < 8; nt++) mma16816(acc[mt][nt], ah, bl[nt]);
                #pragma unroll
                for (int nt = 0; nt < 8; nt++) mma16816(acc[mt][nt], al, bh[nt]);
            }
        }
        __syncthreads();
    }

    #pragma unroll
    for (int mt = 0; mt < 2; mt++)
        #pragma unroll
        for (int nt = 0; nt < 8; nt++) {
            int row = m0 + wm * 32 + mt * 16 + lr;
            int col = e0 + wn * 64 + nt * 8 + lc;
            *(float2*)&Out[((size_t)b * N_ + row) * E_ + col] =
                make_float2(acc[mt][nt][0], acc[mt][nt][1]);
            *(float2*)&Out[((size_t)b * N_ + row + 8) * E_ + col] =
                make_float2(acc[mt][nt][2], acc[mt][nt][3]);
        }
}

// ---------------------------------------------------------------------------
extern "C" void kernel_launch(void* const* d_in, const int* in_sizes, int n_in,
                              void* d_out, int out_size)
{
    const float* x  = (const float*)d_in[0];
    const float* wq = (const float*)d_in[1];
    const float* wk = (const float*)d_in[2];
    const float* wv = (const float*)d_in[3];
    const float* wo = (const float*)d_in[4];
    float* out = (float*)d_out;

    wconv_kernel  <<<192 * 1024 / 4 / 256, 256>>>(wq, wk, wv);
    qkv_mma_kernel<<<M_ / 64, 256>>>(x);
    energy_kernel <<<dim3(SPLITS, B_), 256>>>();
    w2_kernel     <<<dim3(D_, B_), 256>>>(wo);
    out_mma_kernel<<<dim3(N_ / 128, E_ / 128, B_), 256>>>(out);
}